// round 8
// baseline (speedup 1.0000x reference)
#include <cuda_runtime.h>
#include <cuda_bf16.h>
#include <math.h>
#include <stdint.h>

// ---------------- problem constants ----------------
#define BB  16
#define CC  512
#define ICN 256
#define HH  64
#define NN  4096
#define SS  110
#define SP  128     // padded S

// ---------------- scratch (device globals) ----------------
__device__ float         g_tg[(long long)BB * CC * NN];        // theta/g conv out fp32 [B,512,N]
__device__ __nv_bfloat16 g_yTh[(long long)BB * NN * CC];       // y transposed bf16 hi [B,N,C]
__device__ __nv_bfloat16 g_yTl[(long long)BB * NN * CC];
__device__ __nv_bfloat16 g_xTh[(long long)BB * NN * CC];
__device__ __nv_bfloat16 g_xTl[(long long)BB * NN * CC];
__device__ __nv_bfloat16 g_wh[CC * CC];                        // [theta;g] weights [m,k]
__device__ __nv_bfloat16 g_wl[CC * CC];
__device__ __nv_bfloat16 g_wphiTh[CC * ICN];                   // w_phi^T [c, ic]
__device__ __nv_bfloat16 g_wphiTl[CC * ICN];
__device__ __nv_bfloat16 g_wmBh[CC * ICN];                     // w_mask [c, ic] (native)
__device__ __nv_bfloat16 g_wmBl[CC * ICN];
__device__ __nv_bfloat16 g_sppTh[BB * SP * CC];                // spp^T bf16 [B, s(pad), ch]
__device__ __nv_bfloat16 g_sppTl[BB * SP * CC];
__device__ float         g_kkf[BB * SP * CC];                  // kk fp32 [B, s, c]
__device__ __nv_bfloat16 g_kkh[BB * SP * CC];
__device__ __nv_bfloat16 g_kkl[BB * SP * CC];
__device__ float         g_v[BB * SP * CC];                    // v fp32 [B, s, c]
__device__ __nv_bfloat16 g_vTh[BB * CC * SP];                  // v^T bf16 [B, c, s]
__device__ __nv_bfloat16 g_vTl[BB * CC * SP];
__device__ float         g_logits[(long long)BB * SP * NN];    // [B, s(pad), n]
__device__ __nv_bfloat16 g_PTh[(long long)BB * NN * SP];       // exp(logits)^T [B, n, s]
__device__ __nv_bfloat16 g_PTl[(long long)BB * NN * SP];
__device__ float         g_max[BB * SS];
__device__ float         g_invsum[BB * SS];

// ---------------- helpers ----------------
__device__ __forceinline__ uint32_t smem_u32(const void* p) {
    uint32_t a;
    asm("{ .reg .u64 t; cvta.to.shared.u64 t, %1; cvt.u32.u64 %0, t; }" : "=r"(a) : "l"(p));
    return a;
}

#define CP_ASYNC16(saddr, gaddr) \
    asm volatile("cp.async.cg.shared.global [%0], [%1], 16;" :: "r"(saddr), "l"(gaddr))
#define CP_COMMIT() asm volatile("cp.async.commit_group;")
#define CP_WAIT0()  asm volatile("cp.async.wait_group 0;")

#define LDSM4(r0, r1, r2, r3, addr) \
    asm volatile("ldmatrix.sync.aligned.m8n8.x4.shared.b16 {%0,%1,%2,%3}, [%4];" \
                 : "=r"(r0), "=r"(r1), "=r"(r2), "=r"(r3) : "r"(addr))

#define MMA16816(d, a, b) \
    asm volatile("mma.sync.aligned.m16n8k16.row.col.f32.bf16.bf16.f32 " \
                 "{%0,%1,%2,%3}, {%4,%5,%6,%7}, {%8,%9}, {%0,%1,%2,%3};" \
                 : "+f"((d)[0]), "+f"((d)[1]), "+f"((d)[2]), "+f"((d)[3]) \
                 : "r"((a)[0]), "r"((a)[1]), "r"((a)[2]), "r"((a)[3]), \
                   "r"((b)[0]), "r"((b)[1]))

// ---------------- bf16x3 mma.sync GEMM ----------------
// C[m,n] = sum_k A[m,k]*B[n,k]  (both [rows, K] K-contiguous, bf16 hi/lo)
// BM=BN=128, BK=32, 8 warps (2x4, warp tile 64x32), padded smem rows (K32+8).
// 2-stage cp.async double buffer, one barrier per k-tile.
// MMAs issued TERM-MAJOR: 8 independent MMAs between accumulator reuses,
// breaking the 3-deep same-accumulator RAW chains. 2 CTAs/SM.
#define LDP       40                 // padded row length (elements)
#define TILE_B    (128 * LDP * 2)    // 10240 bytes per operand tile
#define STAGE_B   (4 * TILE_B)       // Ah, Al, Bh, Bl
#define GSMEM_BYTES (2 * STAGE_B)    // 81920

template <int ADD>
__global__ void __launch_bounds__(256, 2)
gemm_mma(const __nv_bfloat16* __restrict__ Ah, const __nv_bfloat16* __restrict__ Al,
         long long sA, int lda,
         const __nv_bfloat16* __restrict__ Bh, const __nv_bfloat16* __restrict__ Bl,
         long long sB, int ldb,
         float* __restrict__ C, long long sC, int ldc,
         const float* __restrict__ Cadd, long long sAdd, int K)
{
    extern __shared__ char smem_raw[];
    const uint32_t sb = smem_u32(smem_raw);
    const int tid = threadIdx.x, wid = tid >> 5, lane = tid & 31;
    const int wm = wid & 1, wn = wid >> 1;       // 2 x 4 warp grid
    const int b = blockIdx.z;
    const int bm = blockIdx.y * 128, bn = blockIdx.x * 128;
    Ah += b * sA; Al += b * sA; Bh += b * sB; Bl += b * sB;
    C += b * sC;
    if (ADD) Cadd += b * sAdd;

    const int nkt = K >> 5;

    // cp.async loader for one k-tile into stage buffer
    auto load_stage = [&](int kt, int buf) {
        const uint32_t stg = sb + buf * STAGE_B;
        const int k0 = kt << 5;
#pragma unroll
        for (int i = 0; i < 2; i++) {
            int id = tid + (i << 8);             // 0..511
            int row = id >> 2, cq = (id & 3) << 3;   // cq in elements (8 each)
            uint32_t soff = row * (LDP * 2) + (cq << 1);
            CP_ASYNC16(stg + 0 * TILE_B + soff, (const char*)(Ah + (long long)(bm + row) * lda + k0 + cq));
            CP_ASYNC16(stg + 1 * TILE_B + soff, (const char*)(Al + (long long)(bm + row) * lda + k0 + cq));
            CP_ASYNC16(stg + 2 * TILE_B + soff, (const char*)(Bh + (long long)(bn + row) * ldb + k0 + cq));
            CP_ASYNC16(stg + 3 * TILE_B + soff, (const char*)(Bl + (long long)(bn + row) * ldb + k0 + cq));
        }
    };

    float acc[4][4][4];
#pragma unroll
    for (int mi = 0; mi < 4; mi++)
#pragma unroll
        for (int ni = 0; ni < 4; ni++)
#pragma unroll
            for (int r = 0; r < 4; r++) acc[mi][ni][r] = 0.f;

    // per-lane ldmatrix byte offsets within an operand tile
    const uint32_t a_lb = (wm * 64 + (lane & 15)) * (LDP * 2) + ((lane >> 4) << 4);
    const uint32_t b_lb = (wn * 32 + (lane & 7) + ((lane >> 4) << 3)) * (LDP * 2)
                        + (((lane >> 3) & 1) << 4);

    load_stage(0, 0); CP_COMMIT();

    for (int kt = 0; kt < nkt; kt++) {
        const int buf = kt & 1;
        CP_WAIT0();                      // tile kt resident
        __syncthreads();                 // all warps done with compute(kt-1)
        if (kt + 1 < nkt) {              // prefetch overwrites buffer of kt-1
            load_stage(kt + 1, buf ^ 1); CP_COMMIT();
        }

        const uint32_t stg = sb + buf * STAGE_B;
#pragma unroll
        for (int k16 = 0; k16 < 2; k16++) {
            const uint32_t kb = k16 << 5;        // 16 elements = 32 bytes
            uint32_t bh[4][2], bl[4][2];
#pragma unroll
            for (int p = 0; p < 2; p++) {
                uint32_t bd = stg + 2 * TILE_B + b_lb + p * 16 * (LDP * 2) + kb;
                LDSM4(bh[2 * p][0], bh[2 * p][1], bh[2 * p + 1][0], bh[2 * p + 1][1], bd);
                LDSM4(bl[2 * p][0], bl[2 * p][1], bl[2 * p + 1][0], bl[2 * p + 1][1], bd + TILE_B);
            }
#pragma unroll
            for (int h = 0; h < 2; h++) {
                uint32_t ah[2][4], al[2][4];
#pragma unroll
                for (int m2 = 0; m2 < 2; m2++) {
                    uint32_t ad = stg + a_lb + (h * 2 + m2) * 16 * (LDP * 2) + kb;
                    LDSM4(ah[m2][0], ah[m2][1], ah[m2][2], ah[m2][3], ad);
                    LDSM4(al[m2][0], al[m2][1], al[m2][2], al[m2][3], ad + TILE_B);
                }
                // term-major: 8 independent MMAs between accumulator reuses
#pragma unroll
                for (int m2 = 0; m2 < 2; m2++)
#pragma unroll
                    for (int ni = 0; ni < 4; ni++)
                        MMA16816(acc[h * 2 + m2][ni], ah[m2], bh[ni]);
#pragma unroll
                for (int m2 = 0; m2 < 2; m2++)
#pragma unroll
                    for (int ni = 0; ni < 4; ni++)
                        MMA16816(acc[h * 2 + m2][ni], ah[m2], bl[ni]);
#pragma unroll
                for (int m2 = 0; m2 < 2; m2++)
#pragma unroll
                    for (int ni = 0; ni < 4; ni++)
                        MMA16816(acc[h * 2 + m2][ni], al[m2], bh[ni]);
            }
        }
    }

    // epilogue: fragment layout row = lane/4 (+8), col = 2*(lane%4)
#pragma unroll
    for (int mi = 0; mi < 4; mi++) {
#pragma unroll
        for (int ni = 0; ni < 4; ni++) {
            int r0 = bm + wm * 64 + mi * 16 + (lane >> 2);
            int col = bn + wn * 32 + ni * 8 + ((lane & 3) << 1);
            float2 v01 = make_float2(acc[mi][ni][0], acc[mi][ni][1]);
            float2 v23 = make_float2(acc[mi][ni][2], acc[mi][ni][3]);
            if (ADD) {
                float2 a0 = *reinterpret_cast<const float2*>(Cadd + (long long)r0 * ldc + col);
                float2 a1 = *reinterpret_cast<const float2*>(Cadd + (long long)(r0 + 8) * ldc + col);
                v01.x += a0.x; v01.y += a0.y;
                v23.x += a1.x; v23.y += a1.y;
            }
            *reinterpret_cast<float2*>(C + (long long)r0 * ldc + col) = v01;
            *reinterpret_cast<float2*>(C + (long long)(r0 + 8) * ldc + col) = v23;
        }
    }
}

// ---------------- weight pack + pad zero ----------------
__global__ void pack_kernel(const float* __restrict__ wth, const float* __restrict__ wg,
                            const float* __restrict__ wphi, const float* __restrict__ wmask) {
    int idx = blockIdx.x * 256 + threadIdx.x;
    if (idx < CC * CC) {
        int m = idx / CC, k = idx % CC;
        float w = (m < ICN) ? wth[m * CC + k] : wg[(m - ICN) * CC + k];
        __nv_bfloat16 h = __float2bfloat16(w);
        g_wh[idx] = h;
        g_wl[idx] = __float2bfloat16(w - __bfloat162float(h));
    }
    if (idx < CC * ICN) {
        int c = idx / ICN, ic = idx % ICN;
        float wp = wphi[ic * CC + c];
        __nv_bfloat16 h = __float2bfloat16(wp);
        g_wphiTh[idx] = h;
        g_wphiTl[idx] = __float2bfloat16(wp - __bfloat162float(h));
        float wm = wmask[idx];            // wmask is [c, ic] row-major already
        __nv_bfloat16 hm = __float2bfloat16(wm);
        g_wmBh[idx] = hm;
        g_wmBl[idx] = __float2bfloat16(wm - __bfloat162float(hm));
    }
    if (idx < BB * (SP - SS) * CC) {      // zero spp^T pad rows every launch
        int b = idx / ((SP - SS) * CC);
        int rem = idx % ((SP - SS) * CC);
        int s = SS + rem / CC, c = rem % CC;
        long long o = ((long long)(b * SP) + s) * CC + c;
        g_sppTh[o] = __float2bfloat16(0.f);
        g_sppTl[o] = __float2bfloat16(0.f);
    }
}

// ---------------- fp32 [C, N] -> bf16 hi/lo [N, C] (transpose-convert) ----
__global__ void tconv_kernel(const float* __restrict__ src,
                             __nv_bfloat16* __restrict__ dh, __nv_bfloat16* __restrict__ dl) {
    __shared__ float sm[32][33];
    int n0 = blockIdx.x * 32, c0 = blockIdx.y * 32, b = blockIdx.z;
    int tx = threadIdx.x, ty = threadIdx.y;
    src += (long long)b * CC * NN;
#pragma unroll
    for (int r = 0; r < 4; r++)
        sm[ty + 8 * r][tx] = src[(long long)(c0 + ty + 8 * r) * NN + n0 + tx];
    __syncthreads();
#pragma unroll
    for (int r = 0; r < 4; r++) {
        int n = n0 + ty + 8 * r, c = c0 + tx;
        float v = sm[tx][ty + 8 * r];
        __nv_bfloat16 h = __float2bfloat16(v);
        long long o = ((long long)b * NN + n) * CC + c;
        dh[o] = h;
        dl[o] = __float2bfloat16(v - __bfloat162float(h));
    }
}

// ---------------- SPP pyramid (1/3/6/8) -> bf16 hi/lo transposed ----------
__device__ __forceinline__ void spp_bounds(int s, int& r0, int& r1, int& c0, int& c1) {
    int o, i;
    if (s == 0)      { o = 1; i = 0; }
    else if (s < 10) { o = 3; i = s - 1; }
    else if (s < 46) { o = 6; i = s - 10; }
    else             { o = 8; i = s - 46; }
    int r = i / o, c = i % o;
    r0 = (r * HH) / o; r1 = ((r + 1) * HH + o - 1) / o;
    c0 = (c * HH) / o; c1 = ((c + 1) * HH + o - 1) / o;
}

__global__ void spp_kernel() {
    int bid = blockIdx.x;                       // b*512 + ch
    int b = bid / CC, ch = bid % CC;
    const float* src = g_tg + (long long)bid * NN;
    __shared__ float t[NN];
    __shared__ float red[256];
    int tid = threadIdx.x;
    float mx = -INFINITY;
    for (int i = tid; i < NN; i += 256) {
        float vv = src[i];
        t[i] = vv;
        mx = fmaxf(mx, vv);
    }
    red[tid] = mx;
    __syncthreads();
    for (int st = 128; st > 0; st >>= 1) {
        if (tid < st) red[tid] = fmaxf(red[tid], red[tid + st]);
        __syncthreads();
    }
    if (tid < SS) {
        float out;
        if (tid == 0) out = red[0];
        else {
            int r0, r1, c0, c1;
            spp_bounds(tid, r0, r1, c0, c1);
            out = -INFINITY;
            for (int r = r0; r < r1; r++)
                for (int c = c0; c < c1; c++)
                    out = fmaxf(out, t[r * HH + c]);
        }
        __nv_bfloat16 h = __float2bfloat16(out);
        long long o = ((long long)(b * SP) + tid) * CC + ch;
        g_sppTh[o] = h;
        g_sppTl[o] = __float2bfloat16(out - __bfloat162float(h));
    }
}

// ---------------- kk fp32 -> bf16 hi/lo ----------------
__global__ void kkcvt_kernel() {
    int gid = blockIdx.x * 256 + threadIdx.x;
    if (gid < BB * SP * CC) {
        float v = g_kkf[gid];
        __nv_bfloat16 h = __float2bfloat16(v);
        g_kkh[gid] = h;
        g_kkl[gid] = __float2bfloat16(v - __bfloat162float(h));
    }
}

// ---------------- row stats: max + 1/sum(exp) per (b,s) ----------------
__global__ void rowstat_kernel() {
    int s = blockIdx.x, b = blockIdx.y;
    const float* row = g_logits + ((long long)(b * SP + s)) * NN;
    __shared__ float t[NN];
    __shared__ float red[256];
    int tid = threadIdx.x;
    float mx = -INFINITY;
    for (int i = tid; i < NN; i += 256) {
        float v = row[i];
        t[i] = v;
        mx = fmaxf(mx, v);
    }
    red[tid] = mx;
    __syncthreads();
    for (int st = 128; st > 0; st >>= 1) {
        if (tid < st) red[tid] = fmaxf(red[tid], red[tid + st]);
        __syncthreads();
    }
    mx = red[0];
    __syncthreads();
    float sum = 0.f;
    for (int i = tid; i < NN; i += 256) sum += __expf(t[i] - mx);
    red[tid] = sum;
    __syncthreads();
    for (int st = 128; st > 0; st >>= 1) {
        if (tid < st) red[tid] += red[tid + st];
        __syncthreads();
    }
    if (tid == 0) {
        g_max[b * SS + s] = mx;
        g_invsum[b * SS + s] = 1.0f / red[0];
    }
}

// ---------------- exp + transpose: logits [s,n] -> PT bf16 [n,s] ----------
__global__ void texp_kernel() {
    __shared__ float sm[32][SP + 1];
    __shared__ float gmx[SP];
    int b = blockIdx.y, n0 = blockIdx.x * 32;
    int tid = threadIdx.x;
    if (tid < SS) gmx[tid] = g_max[b * SS + tid];
    __syncthreads();
    int tx = tid & 31, ty = tid >> 5;          // ty 0..7
#pragma unroll
    for (int r = 0; r < 16; r++) {
        int s = ty + (r << 3);
        float e = 0.f;
        if (s < SS)
            e = __expf(g_logits[((long long)(b * SP + s)) * NN + n0 + tx] - gmx[s]);
        sm[tx][s] = e;
    }
    __syncthreads();
#pragma unroll
    for (int w = 0; w < 16; w++) {
        int idx = tid + (w << 8);
        int nl = idx >> 7, s = idx & 127;
        float v = sm[nl][s];
        __nv_bfloat16 h = __float2bfloat16(v);
        long long o = ((long long)(b * NN) + n0 + nl) * SP + s;
        g_PTh[o] = h;
        g_PTl[o] = __float2bfloat16(v - __bfloat162float(h));
    }
}

// ---------------- v [s,c] * invsum -> vT bf16 hi/lo [c,s] ----------------
__global__ void vt_kernel() {
    int gid = blockIdx.x * 256 + threadIdx.x;
    if (gid >= BB * CC * SP) return;
    int b = gid >> 16;                // CC*SP = 65536
    int rem = gid & 65535;
    int c = rem >> 7, s = rem & 127;
    float val = 0.f;
    if (s < SS)
        val = g_v[((long long)(b * SP + s)) * CC + c] * g_invsum[b * SS + s];
    __nv_bfloat16 h = __float2bfloat16(val);
    long long o = ((long long)b * CC + c) * SP + s;
    g_vTh[o] = h;
    g_vTl[o] = __float2bfloat16(val - __bfloat162float(h));
}

// ---------------- launch ----------------
extern "C" void kernel_launch(void* const* d_in, const int* in_sizes, int n_in,
                              void* d_out, int out_size) {
    const float* x     = (const float*)d_in[0];
    const float* y     = (const float*)d_in[1];
    const float* wphi  = (const float*)d_in[2];
    const float* wth   = (const float*)d_in[3];
    const float* wg    = (const float*)d_in[4];
    const float* wmask = (const float*)d_in[5];
    float* out = (float*)d_out;

    cudaFuncSetAttribute(gemm_mma<0>, cudaFuncAttributeMaxDynamicSharedMemorySize, GSMEM_BYTES);
    cudaFuncSetAttribute(gemm_mma<1>, cudaFuncAttributeMaxDynamicSharedMemorySize, GSMEM_BYTES);

    float *tg, *kkf, *v, *logits;
    __nv_bfloat16 *yTh, *yTl, *xTh, *xTl, *wh, *wl, *wpTh, *wpTl, *wmBh, *wmBl;
    __nv_bfloat16 *spTh, *spTl, *kkh, *kkl, *vTh, *vTl, *PTh, *PTl;
    cudaGetSymbolAddress((void**)&tg, g_tg);
    cudaGetSymbolAddress((void**)&kkf, g_kkf);
    cudaGetSymbolAddress((void**)&v, g_v);
    cudaGetSymbolAddress((void**)&logits, g_logits);
    cudaGetSymbolAddress((void**)&yTh, g_yTh);   cudaGetSymbolAddress((void**)&yTl, g_yTl);
    cudaGetSymbolAddress((void**)&xTh, g_xTh);   cudaGetSymbolAddress((void**)&xTl, g_xTl);
    cudaGetSymbolAddress((void**)&wh, g_wh);     cudaGetSymbolAddress((void**)&wl, g_wl);
    cudaGetSymbolAddress((void**)&wpTh, g_wphiTh); cudaGetSymbolAddress((void**)&wpTl, g_wphiTl);
    cudaGetSymbolAddress((void**)&wmBh, g_wmBh); cudaGetSymbolAddress((void**)&wmBl, g_wmBl);
    cudaGetSymbolAddress((void**)&spTh, g_sppTh); cudaGetSymbolAddress((void**)&spTl, g_sppTl);
    cudaGetSymbolAddress((void**)&kkh, g_kkh);   cudaGetSymbolAddress((void**)&kkl, g_kkl);
    cudaGetSymbolAddress((void**)&vTh, g_vTh);   cudaGetSymbolAddress((void**)&vTl, g_vTl);
    cudaGetSymbolAddress((void**)&PTh, g_PTh);   cudaGetSymbolAddress((void**)&PTl, g_PTl);

    // 0. pack weights, zero spp pad rows
    pack_kernel<<<(CC * CC + 255) / 256, 256>>>(wth, wg, wphi, wmask);

    // 1. transpose-convert y and x to bf16 hi/lo [N, C]
    tconv_kernel<<<dim3(NN / 32, CC / 32, BB), dim3(32, 8)>>>(y, yTh, yTl);
    tconv_kernel<<<dim3(NN / 32, CC / 32, BB), dim3(32, 8)>>>(x, xTh, xTl);

    // 2. tg[m,n] = sum_c W_tg[m,c] * y[c,n]     (M=512, N=4096, K=512)
    gemm_mma<0><<<dim3(NN / 128, CC / 128, BB), 256, GSMEM_BYTES>>>(
        wh, wl, 0LL, CC, yTh, yTl, (long long)NN * CC, CC,
        tg, (long long)CC * NN, NN, nullptr, 0LL, CC);

    // 3. SPP pyramid -> spp^T bf16 hi/lo [B, s, ch]
    spp_kernel<<<BB * CC, 256>>>();

    // 4. kk[s,c] = sum_ic sppT[s,ic(theta)] * wphiT[c,ic]   (M=128, N=512, K=256)
    gemm_mma<0><<<dim3(CC / 128, 1, BB), 256, GSMEM_BYTES>>>(
        spTh, spTl, (long long)SP * CC, CC, wpTh, wpTl, 0LL, ICN,
        kkf, (long long)SP * CC, CC, nullptr, 0LL, ICN);
    kkcvt_kernel<<<(BB * SP * CC + 255) / 256, 256>>>();

    // 5. v[s,c] = sum_ic sppT[s, 256+ic(g)] * wmask[c,ic]   (M=128, N=512, K=256)
    gemm_mma<0><<<dim3(CC / 128, 1, BB), 256, GSMEM_BYTES>>>(
        spTh + ICN, spTl + ICN, (long long)SP * CC, CC, wmBh, wmBl, 0LL, ICN,
        v, (long long)SP * CC, CC, nullptr, 0LL, ICN);

    // 6. logits[s,n] = sum_c kk[s,c] * x[c,n]   (M=128, N=4096, K=512)
    gemm_mma<0><<<dim3(NN / 128, 1, BB), 256, GSMEM_BYTES>>>(
        kkh, kkl, (long long)SP * CC, CC, xTh, xTl, (long long)NN * CC, CC,
        logits, (long long)SP * NN, NN, nullptr, 0LL, CC);

    // 7. per-(b,s) max + 1/sum(exp)
    rowstat_kernel<<<dim3(SS, BB), 256>>>();

    // 8. exp + transpose -> PT bf16 hi/lo [n, s]
    texp_kernel<<<dim3(NN / 32, BB), 256>>>();

    // 9. scale v by invsum, transpose -> vT bf16 hi/lo [c, s]
    vt_kernel<<<(BB * CC * SP + 255) / 256, 256>>>();

    // 10. out[c,n] = x[c,n] + sum_s vT[c,s] * PT[n,s]   (M=512, N=4096, K=128)
    gemm_mma<1><<<dim3(NN / 128, CC / 128, BB), 256, GSMEM_BYTES>>>(
        vTh, vTl, (long long)CC * SP, SP, PTh, PTl, (long long)NN * SP, SP,
        out, (long long)CC * NN, NN, x, (long long)CC * NN, SP);
}

// round 11
// speedup vs baseline: 1.0218x; 1.0218x over previous
#include <cuda_runtime.h>
#include <cuda_bf16.h>
#include <math.h>
#include <stdint.h>

// ---------------- problem constants ----------------
#define BB  16
#define CC  512
#define ICN 256
#define HH  64
#define NN  4096
#define SS  110
#define SP  128     // padded S

// ---------------- scratch (device globals) ----------------
__device__ float         g_tg[(long long)BB * CC * NN];        // theta/g conv out fp32 [B,512,N]
__device__ __nv_bfloat16 g_yTh[(long long)BB * NN * CC];       // y transposed bf16 hi [B,N,C]
__device__ __nv_bfloat16 g_yTl[(long long)BB * NN * CC];
__device__ __nv_bfloat16 g_xTh[(long long)BB * NN * CC];
__device__ __nv_bfloat16 g_xTl[(long long)BB * NN * CC];
__device__ __nv_bfloat16 g_wh[CC * CC];                        // [theta;g] weights [m,k]
__device__ __nv_bfloat16 g_wl[CC * CC];
__device__ __nv_bfloat16 g_wphiTh[CC * ICN];                   // w_phi^T [c, ic]
__device__ __nv_bfloat16 g_wphiTl[CC * ICN];
__device__ __nv_bfloat16 g_wmBh[CC * ICN];                     // w_mask [c, ic] (native)
__device__ __nv_bfloat16 g_wmBl[CC * ICN];
__device__ __nv_bfloat16 g_sppTh[BB * SP * CC];                // spp^T bf16 [B, s(pad), ch]
__device__ __nv_bfloat16 g_sppTl[BB * SP * CC];
__device__ __nv_bfloat16 g_kkh[BB * SP * CC];                  // kk bf16 hi/lo [B, s, c]
__device__ __nv_bfloat16 g_kkl[BB * SP * CC];
__device__ float         g_v[BB * SP * CC];                    // v fp32 [B, s, c]
__device__ __nv_bfloat16 g_vTh[BB * CC * SP];                  // v^T bf16 [B, c, s]
__device__ __nv_bfloat16 g_vTl[BB * CC * SP];
__device__ float         g_logits[(long long)BB * SP * NN];    // [B, s(pad), n]
__device__ __nv_bfloat16 g_PTh[(long long)BB * NN * SP];       // exp(logits)^T [B, n, s]
__device__ __nv_bfloat16 g_PTl[(long long)BB * NN * SP];
__device__ float         g_max[BB * SS];
__device__ float         g_invsum[BB * SS];

// ---------------- helpers ----------------
__device__ __forceinline__ uint32_t smem_u32(const void* p) {
    uint32_t a;
    asm("{ .reg .u64 t; cvta.to.shared.u64 t, %1; cvt.u32.u64 %0, t; }" : "=r"(a) : "l"(p));
    return a;
}

#define CP_ASYNC16(saddr, gaddr) \
    asm volatile("cp.async.cg.shared.global [%0], [%1], 16;" :: "r"(saddr), "l"(gaddr))
#define CP_COMMIT() asm volatile("cp.async.commit_group;")
#define CP_WAIT0()  asm volatile("cp.async.wait_group 0;")

#define LDSM4(r0, r1, r2, r3, addr) \
    asm volatile("ldmatrix.sync.aligned.m8n8.x4.shared.b16 {%0,%1,%2,%3}, [%4];" \
                 : "=r"(r0), "=r"(r1), "=r"(r2), "=r"(r3) : "r"(addr))

#define MMA16816(d, a, b) \
    asm volatile("mma.sync.aligned.m16n8k16.row.col.f32.bf16.bf16.f32 " \
                 "{%0,%1,%2,%3}, {%4,%5,%6,%7}, {%8,%9}, {%0,%1,%2,%3};" \
                 : "+f"((d)[0]), "+f"((d)[1]), "+f"((d)[2]), "+f"((d)[3]) \
                 : "r"((a)[0]), "r"((a)[1]), "r"((a)[2]), "r"((a)[3]), \
                   "r"((b)[0]), "r"((b)[1]))

// ---------------- bf16x3 mma.sync GEMM ----------------
// C[m,n] = sum_k A[m,k]*B[n,k]  (both [rows, K] K-contiguous, bf16 hi/lo)
// BM=BN=128, BK=32, 8 warps (2x4, warp tile 64x32), padded smem rows (K32+8).
// 2-stage cp.async double buffer, one barrier per k-tile. 2 CTAs/SM.
// OUTBF=1: write bf16 hi/lo pairs (Ch/Cl) instead of fp32 C.
#define LDP       40                 // padded row length (elements)
#define TILE_B    (128 * LDP * 2)    // 10240 bytes per operand tile
#define STAGE_B   (4 * TILE_B)       // Ah, Al, Bh, Bl
#define GSMEM_BYTES (2 * STAGE_B)    // 81920

template <int ADD, int OUTBF>
__global__ void __launch_bounds__(256, 2)
gemm_mma(const __nv_bfloat16* __restrict__ Ah, const __nv_bfloat16* __restrict__ Al,
         long long sA, int lda,
         const __nv_bfloat16* __restrict__ Bh, const __nv_bfloat16* __restrict__ Bl,
         long long sB, int ldb,
         float* __restrict__ C,
         __nv_bfloat16* __restrict__ Ch, __nv_bfloat16* __restrict__ Cl,
         long long sC, int ldc,
         const float* __restrict__ Cadd, long long sAdd, int K)
{
    extern __shared__ char smem_raw[];
    const uint32_t sb = smem_u32(smem_raw);
    const int tid = threadIdx.x, wid = tid >> 5, lane = tid & 31;
    const int wm = wid & 1, wn = wid >> 1;       // 2 x 4 warp grid
    const int b = blockIdx.z;
    const int bm = blockIdx.y * 128, bn = blockIdx.x * 128;
    Ah += b * sA; Al += b * sA; Bh += b * sB; Bl += b * sB;
    if (OUTBF) { Ch += b * sC; Cl += b * sC; } else { C += b * sC; }
    if (ADD) Cadd += b * sAdd;

    const int nkt = K >> 5;

    // cp.async loader for one k-tile into stage buffer
    auto load_stage = [&](int kt, int buf) {
        const uint32_t stg = sb + buf * STAGE_B;
        const int k0 = kt << 5;
#pragma unroll
        for (int i = 0; i < 2; i++) {
            int id = tid + (i << 8);             // 0..511
            int row = id >> 2, cq = (id & 3) << 3;   // cq in elements (8 each)
            uint32_t soff = row * (LDP * 2) + (cq << 1);
            CP_ASYNC16(stg + 0 * TILE_B + soff, (const char*)(Ah + (long long)(bm + row) * lda + k0 + cq));
            CP_ASYNC16(stg + 1 * TILE_B + soff, (const char*)(Al + (long long)(bm + row) * lda + k0 + cq));
            CP_ASYNC16(stg + 2 * TILE_B + soff, (const char*)(Bh + (long long)(bn + row) * ldb + k0 + cq));
            CP_ASYNC16(stg + 3 * TILE_B + soff, (const char*)(Bl + (long long)(bn + row) * ldb + k0 + cq));
        }
    };

    float acc[4][4][4];
#pragma unroll
    for (int mi = 0; mi < 4; mi++)
#pragma unroll
        for (int ni = 0; ni < 4; ni++)
#pragma unroll
            for (int r = 0; r < 4; r++) acc[mi][ni][r] = 0.f;

    // per-lane ldmatrix byte offsets within an operand tile
    const uint32_t a_lb = (wm * 64 + (lane & 15)) * (LDP * 2) + ((lane >> 4) << 4);
    const uint32_t b_lb = (wn * 32 + (lane & 7) + ((lane >> 4) << 3)) * (LDP * 2)
                        + (((lane >> 3) & 1) << 4);

    load_stage(0, 0); CP_COMMIT();

    for (int kt = 0; kt < nkt; kt++) {
        const int buf = kt & 1;
        CP_WAIT0();                      // tile kt resident
        __syncthreads();                 // all warps done with compute(kt-1)
        if (kt + 1 < nkt) {              // prefetch overwrites buffer of kt-1
            load_stage(kt + 1, buf ^ 1); CP_COMMIT();
        }

        const uint32_t stg = sb + buf * STAGE_B;
#pragma unroll
        for (int k16 = 0; k16 < 2; k16++) {
            const uint32_t kb = k16 << 5;        // 16 elements = 32 bytes
            uint32_t bh[4][2], bl[4][2];
#pragma unroll
            for (int p = 0; p < 2; p++) {
                uint32_t bd = stg + 2 * TILE_B + b_lb + p * 16 * (LDP * 2) + kb;
                LDSM4(bh[2 * p][0], bh[2 * p][1], bh[2 * p + 1][0], bh[2 * p + 1][1], bd);
                LDSM4(bl[2 * p][0], bl[2 * p][1], bl[2 * p + 1][0], bl[2 * p + 1][1], bd + TILE_B);
            }
#pragma unroll
            for (int h = 0; h < 2; h++) {
                uint32_t ah[2][4], al[2][4];
#pragma unroll
                for (int m2 = 0; m2 < 2; m2++) {
                    uint32_t ad = stg + a_lb + (h * 2 + m2) * 16 * (LDP * 2) + kb;
                    LDSM4(ah[m2][0], ah[m2][1], ah[m2][2], ah[m2][3], ad);
                    LDSM4(al[m2][0], al[m2][1], al[m2][2], al[m2][3], ad + TILE_B);
                }
#pragma unroll
                for (int m2 = 0; m2 < 2; m2++)
#pragma unroll
                    for (int ni = 0; ni < 4; ni++)
                        MMA16816(acc[h * 2 + m2][ni], ah[m2], bh[ni]);
#pragma unroll
                for (int m2 = 0; m2 < 2; m2++)
#pragma unroll
                    for (int ni = 0; ni < 4; ni++)
                        MMA16816(acc[h * 2 + m2][ni], ah[m2], bl[ni]);
#pragma unroll
                for (int m2 = 0; m2 < 2; m2++)
#pragma unroll
                    for (int ni = 0; ni < 4; ni++)
                        MMA16816(acc[h * 2 + m2][ni], al[m2], bh[ni]);
            }
        }
    }

    // epilogue: fragment layout row = lane/4 (+8), col = 2*(lane%4)
#pragma unroll
    for (int mi = 0; mi < 4; mi++) {
#pragma unroll
        for (int ni = 0; ni < 4; ni++) {
            int r0 = bm + wm * 64 + mi * 16 + (lane >> 2);
            int col = bn + wn * 32 + ni * 8 + ((lane & 3) << 1);
            float2 v01 = make_float2(acc[mi][ni][0], acc[mi][ni][1]);
            float2 v23 = make_float2(acc[mi][ni][2], acc[mi][ni][3]);
            if (OUTBF) {
                __nv_bfloat16 h0 = __float2bfloat16(v01.x), h1 = __float2bfloat16(v01.y);
                __nv_bfloat16 h2 = __float2bfloat16(v23.x), h3 = __float2bfloat16(v23.y);
                __nv_bfloat162 p0; p0.x = h0; p0.y = h1;
                __nv_bfloat162 p1; p1.x = h2; p1.y = h3;
                *reinterpret_cast<__nv_bfloat162*>(Ch + (long long)r0 * ldc + col) = p0;
                *reinterpret_cast<__nv_bfloat162*>(Ch + (long long)(r0 + 8) * ldc + col) = p1;
                __nv_bfloat162 q0, q1;
                q0.x = __float2bfloat16(v01.x - __bfloat162float(h0));
                q0.y = __float2bfloat16(v01.y - __bfloat162float(h1));
                q1.x = __float2bfloat16(v23.x - __bfloat162float(h2));
                q1.y = __float2bfloat16(v23.y - __bfloat162float(h3));
                *reinterpret_cast<__nv_bfloat162*>(Cl + (long long)r0 * ldc + col) = q0;
                *reinterpret_cast<__nv_bfloat162*>(Cl + (long long)(r0 + 8) * ldc + col) = q1;
            } else {
                if (ADD) {
                    float2 a0 = *reinterpret_cast<const float2*>(Cadd + (long long)r0 * ldc + col);
                    float2 a1 = *reinterpret_cast<const float2*>(Cadd + (long long)(r0 + 8) * ldc + col);
                    v01.x += a0.x; v01.y += a0.y;
                    v23.x += a1.x; v23.y += a1.y;
                }
                *reinterpret_cast<float2*>(C + (long long)r0 * ldc + col) = v01;
                *reinterpret_cast<float2*>(C + (long long)(r0 + 8) * ldc + col) = v23;
            }
        }
    }
}

// ---------------- weight pack + pad zero ----------------
__global__ void pack_kernel(const float* __restrict__ wth, const float* __restrict__ wg,
                            const float* __restrict__ wphi, const float* __restrict__ wmask) {
    int idx = blockIdx.x * 256 + threadIdx.x;
    if (idx < CC * CC) {
        int m = idx / CC, k = idx % CC;
        float w = (m < ICN) ? wth[m * CC + k] : wg[(m - ICN) * CC + k];
        __nv_bfloat16 h = __float2bfloat16(w);
        g_wh[idx] = h;
        g_wl[idx] = __float2bfloat16(w - __bfloat162float(h));
    }
    if (idx < CC * ICN) {
        int c = idx / ICN, ic = idx % ICN;
        float wp = wphi[ic * CC + c];
        __nv_bfloat16 h = __float2bfloat16(wp);
        g_wphiTh[idx] = h;
        g_wphiTl[idx] = __float2bfloat16(wp - __bfloat162float(h));
        float wm = wmask[idx];            // wmask is [c, ic] row-major already
        __nv_bfloat16 hm = __float2bfloat16(wm);
        g_wmBh[idx] = hm;
        g_wmBl[idx] = __float2bfloat16(wm - __bfloat162float(hm));
    }
    if (idx < BB * (SP - SS) * CC) {      // zero spp^T pad rows every launch
        int b = idx / ((SP - SS) * CC);
        int rem = idx % ((SP - SS) * CC);
        int s = SS + rem / CC, c = rem % CC;
        long long o = ((long long)(b * SP) + s) * CC + c;
        g_sppTh[o] = __float2bfloat16(0.f);
        g_sppTl[o] = __float2bfloat16(0.f);
    }
}

// ---------------- fp32 [C, N] -> bf16 hi/lo [N, C] (transpose-convert) ----
__global__ void tconv_kernel(const float* __restrict__ src,
                             __nv_bfloat16* __restrict__ dh, __nv_bfloat16* __restrict__ dl) {
    __shared__ float sm[32][33];
    int n0 = blockIdx.x * 32, c0 = blockIdx.y * 32, b = blockIdx.z;
    int tx = threadIdx.x, ty = threadIdx.y;
    src += (long long)b * CC * NN;
#pragma unroll
    for (int r = 0; r < 4; r++)
        sm[ty + 8 * r][tx] = src[(long long)(c0 + ty + 8 * r) * NN + n0 + tx];
    __syncthreads();
#pragma unroll
    for (int r = 0; r < 4; r++) {
        int n = n0 + ty + 8 * r, c = c0 + tx;
        float v = sm[tx][ty + 8 * r];
        __nv_bfloat16 h = __float2bfloat16(v);
        long long o = ((long long)b * NN + n) * CC + c;
        dh[o] = h;
        dl[o] = __float2bfloat16(v - __bfloat162float(h));
    }
}

// ---------------- SPP pyramid (1/3/6/8) -> bf16 hi/lo transposed ----------
__device__ __forceinline__ void spp_bounds(int s, int& r0, int& r1, int& c0, int& c1) {
    int o, i;
    if (s == 0)      { o = 1; i = 0; }
    else if (s < 10) { o = 3; i = s - 1; }
    else if (s < 46) { o = 6; i = s - 10; }
    else             { o = 8; i = s - 46; }
    int r = i / o, c = i % o;
    r0 = (r * HH) / o; r1 = ((r + 1) * HH + o - 1) / o;
    c0 = (c * HH) / o; c1 = ((c + 1) * HH + o - 1) / o;
}

__global__ void spp_kernel() {
    int bid = blockIdx.x;                       // b*512 + ch
    int b = bid / CC, ch = bid % CC;
    const float* src = g_tg + (long long)bid * NN;
    __shared__ float t[NN];
    __shared__ float red[256];
    int tid = threadIdx.x;
    float mx = -INFINITY;
    for (int i = tid; i < NN; i += 256) {
        float vv = src[i];
        t[i] = vv;
        mx = fmaxf(mx, vv);
    }
    red[tid] = mx;
    __syncthreads();
    for (int st = 128; st > 0; st >>= 1) {
        if (tid < st) red[tid] = fmaxf(red[tid], red[tid + st]);
        __syncthreads();
    }
    if (tid < SS) {
        float out;
        if (tid == 0) out = red[0];
        else {
            int r0, r1, c0, c1;
            spp_bounds(tid, r0, r1, c0, c1);
            out = -INFINITY;
            for (int r = r0; r < r1; r++)
                for (int c = c0; c < c1; c++)
                    out = fmaxf(out, t[r * HH + c]);
        }
        __nv_bfloat16 h = __float2bfloat16(out);
        long long o = ((long long)(b * SP) + tid) * CC + ch;
        g_sppTh[o] = h;
        g_sppTl[o] = __float2bfloat16(out - __bfloat162float(h));
    }
}

// ---------------- row stats: max + 1/sum(exp) per (b,s) ----------------
__global__ void rowstat_kernel() {
    int s = blockIdx.x, b = blockIdx.y;
    const float* row = g_logits + ((long long)(b * SP + s)) * NN;
    __shared__ float t[NN];
    __shared__ float red[256];
    int tid = threadIdx.x;
    float mx = -INFINITY;
    for (int i = tid; i < NN; i += 256) {
        float v = row[i];
        t[i] = v;
        mx = fmaxf(mx, v);
    }
    red[tid] = mx;
    __syncthreads();
    for (int st = 128; st > 0; st >>= 1) {
        if (tid < st) red[tid] = fmaxf(red[tid], red[tid + st]);
        __syncthreads();
    }
    mx = red[0];
    __syncthreads();
    float sum = 0.f;
    for (int i = tid; i < NN; i += 256) sum += __expf(t[i] - mx);
    red[tid] = sum;
    __syncthreads();
    for (int st = 128; st > 0; st >>= 1) {
        if (tid < st) red[tid] += red[tid + st];
        __syncthreads();
    }
    if (tid == 0) {
        g_max[b * SS + s] = mx;
        g_invsum[b * SS + s] = 1.0f / red[0];
    }
}

// ---------------- exp + transpose: logits [s,n] -> PT bf16 [n,s] ----------
__global__ void texp_kernel() {
    __shared__ float sm[32][SP + 1];
    __shared__ float gmx[SP];
    int b = blockIdx.y, n0 = blockIdx.x * 32;
    int tid = threadIdx.x;
    if (tid < SS) gmx[tid] = g_max[b * SS + tid];
    __syncthreads();
    int tx = tid & 31, ty = tid >> 5;          // ty 0..7
#pragma unroll
    for (int r = 0; r < 16; r++) {
        int s = ty + (r << 3);
        float e = 0.f;
        if (s < SS)
            e = __expf(g_logits[((long long)(b * SP + s)) * NN + n0 + tx] - gmx[s]);
        sm[tx][s] = e;
    }
    __syncthreads();
#pragma unroll
    for (int w = 0; w < 16; w++) {
        int idx = tid + (w << 8);
        int nl = idx >> 7, s = idx & 127;
        float v = sm[nl][s];
        __nv_bfloat16 h = __float2bfloat16(v);
        long long o = ((long long)(b * NN) + n0 + nl) * SP + s;
        g_PTh[o] = h;
        g_PTl[o] = __float2bfloat16(v - __bfloat162float(h));
    }
}

// ---------------- v [s,c] * invsum -> vT bf16 hi/lo [c,s] ----------------
__global__ void vt_kernel() {
    int gid = blockIdx.x * 256 + threadIdx.x;
    if (gid >= BB * CC * SP) return;
    int b = gid >> 16;                // CC*SP = 65536
    int rem = gid & 65535;
    int c = rem >> 7, s = rem & 127;
    float val = 0.f;
    if (s < SS)
        val = g_v[((long long)(b * SP + s)) * CC + c] * g_invsum[b * SS + s];
    __nv_bfloat16 h = __float2bfloat16(val);
    long long o = ((long long)b * CC + c) * SP + s;
    g_vTh[o] = h;
    g_vTl[o] = __float2bfloat16(val - __bfloat162float(h));
}

// ---------------- launch ----------------
extern "C" void kernel_launch(void* const* d_in, const int* in_sizes, int n_in,
                              void* d_out, int out_size) {
    const float* x     = (const float*)d_in[0];
    const float* y     = (const float*)d_in[1];
    const float* wphi  = (const float*)d_in[2];
    const float* wth   = (const float*)d_in[3];
    const float* wg    = (const float*)d_in[4];
    const float* wmask = (const float*)d_in[5];
    float* out = (float*)d_out;

    // one-time resources (host-side; not captured operations)
    static cudaStream_t s1 = nullptr, s2 = nullptr;
    static cudaEvent_t ev0, ev1, evSpp, evRow, ev3;
    if (!s1) {
        cudaStreamCreateWithFlags(&s1, cudaStreamNonBlocking);
        cudaStreamCreateWithFlags(&s2, cudaStreamNonBlocking);
        cudaEventCreateWithFlags(&ev0,   cudaEventDisableTiming);
        cudaEventCreateWithFlags(&ev1,   cudaEventDisableTiming);
        cudaEventCreateWithFlags(&evSpp, cudaEventDisableTiming);
        cudaEventCreateWithFlags(&evRow, cudaEventDisableTiming);
        cudaEventCreateWithFlags(&ev3,   cudaEventDisableTiming);
        cudaFuncSetAttribute(gemm_mma<0,0>, cudaFuncAttributeMaxDynamicSharedMemorySize, GSMEM_BYTES);
        cudaFuncSetAttribute(gemm_mma<1,0>, cudaFuncAttributeMaxDynamicSharedMemorySize, GSMEM_BYTES);
        cudaFuncSetAttribute(gemm_mma<0,1>, cudaFuncAttributeMaxDynamicSharedMemorySize, GSMEM_BYTES);
    }

    float *tg, *v, *logits;
    __nv_bfloat16 *yTh, *yTl, *xTh, *xTl, *wh, *wl, *wpTh, *wpTl, *wmBh, *wmBl;
    __nv_bfloat16 *spTh, *spTl, *kkh, *kkl, *vTh, *vTl, *PTh, *PTl;
    cudaGetSymbolAddress((void**)&tg, g_tg);
    cudaGetSymbolAddress((void**)&v, g_v);
    cudaGetSymbolAddress((void**)&logits, g_logits);
    cudaGetSymbolAddress((void**)&yTh, g_yTh);   cudaGetSymbolAddress((void**)&yTl, g_yTl);
    cudaGetSymbolAddress((void**)&xTh, g_xTh);   cudaGetSymbolAddress((void**)&xTl, g_xTl);
    cudaGetSymbolAddress((void**)&wh, g_wh);     cudaGetSymbolAddress((void**)&wl, g_wl);
    cudaGetSymbolAddress((void**)&wpTh, g_wphiTh); cudaGetSymbolAddress((void**)&wpTl, g_wphiTl);
    cudaGetSymbolAddress((void**)&wmBh, g_wmBh); cudaGetSymbolAddress((void**)&wmBl, g_wmBl);
    cudaGetSymbolAddress((void**)&spTh, g_sppTh); cudaGetSymbolAddress((void**)&spTl, g_sppTl);
    cudaGetSymbolAddress((void**)&kkh, g_kkh);   cudaGetSymbolAddress((void**)&kkl, g_kkl);
    cudaGetSymbolAddress((void**)&vTh, g_vTh);   cudaGetSymbolAddress((void**)&vTl, g_vTl);
    cudaGetSymbolAddress((void**)&PTh, g_PTh);   cudaGetSymbolAddress((void**)&PTl, g_PTl);

    // ---- fork: tconv_x on s1 (depends only on input x) ----
    cudaEventRecord(ev0, 0);
    cudaStreamWaitEvent(s1, ev0, 0);
    tconv_kernel<<<dim3(NN / 32, CC / 32, BB), dim3(32, 8), 0, s1>>>(x, xTh, xTl);
    cudaEventRecord(ev1, s1);

    // ---- main chain on default stream ----
    pack_kernel<<<(CC * CC + 255) / 256, 256>>>(wth, wg, wphi, wmask);
    tconv_kernel<<<dim3(NN / 32, CC / 32, BB), dim3(32, 8)>>>(y, yTh, yTl);

    // conv GEMM: tg = W_tg @ y   (M=512, N=4096, K=512)
    gemm_mma<0,0><<<dim3(NN / 128, CC / 128, BB), 256, GSMEM_BYTES>>>(
        wh, wl, 0LL, CC, yTh, yTl, (long long)NN * CC, CC,
        tg, nullptr, nullptr, (long long)CC * NN, NN, nullptr, 0LL, CC);

    spp_kernel<<<BB * CC, 256>>>();

    // ---- fork: v chain on s2 (needs pack + spp, both before evSpp) ----
    cudaEventRecord(evSpp, 0);
    cudaStreamWaitEvent(s2, evSpp, 0);
    gemm_mma<0,0><<<dim3(CC / 128, 1, BB), 256, GSMEM_BYTES, s2>>>(
        spTh + ICN, spTl + ICN, (long long)SP * CC, CC, wmBh, wmBl, 0LL, ICN,
        v, nullptr, nullptr, (long long)SP * CC, CC, nullptr, 0LL, ICN);

    // kk GEMM with fused bf16 hi/lo output  (M=128, N=512, K=256)
    gemm_mma<0,1><<<dim3(CC / 128, 1, BB), 256, GSMEM_BYTES>>>(
        spTh, spTl, (long long)SP * CC, CC, wpTh, wpTl, 0LL, ICN,
        nullptr, kkh, kkl, (long long)SP * CC, CC, nullptr, 0LL, ICN);

    // join: logits GEMM needs xT
    cudaStreamWaitEvent(0, ev1, 0);
    gemm_mma<0,0><<<dim3(NN / 128, 1, BB), 256, GSMEM_BYTES>>>(
        kkh, kkl, (long long)SP * CC, CC, xTh, xTl, (long long)NN * CC, CC,
        logits, nullptr, nullptr, (long long)SP * NN, NN, nullptr, 0LL, CC);

    rowstat_kernel<<<dim3(SS, BB), 256>>>();

    // ---- fork: vt on s2 (needs vGEMM [s2 order] + rowstat invsum) ----
    cudaEventRecord(evRow, 0);
    cudaStreamWaitEvent(s2, evRow, 0);
    vt_kernel<<<(BB * CC * SP + 255) / 256, 256, 0, s2>>>();
    cudaEventRecord(ev3, s2);

    texp_kernel<<<dim3(NN / 32, BB), 256>>>();

    // join: output GEMM needs vT + PT
    cudaStreamWaitEvent(0, ev3, 0);
    gemm_mma<1,0><<<dim3(NN / 128, CC / 128, BB), 256, GSMEM_BYTES>>>(
        vTh, vTl, (long long)CC * SP, SP, PTh, PTl, (long long)NN * SP, SP,
        out, nullptr, nullptr, (long long)CC * NN, NN, x, (long long)CC * NN, SP);
}

// round 12
// speedup vs baseline: 1.1738x; 1.1488x over previous
#include <cuda_runtime.h>
#include <cuda_bf16.h>
#include <math.h>
#include <stdint.h>

// ---------------- problem constants ----------------
#define BB  16
#define CC  512
#define ICN 256
#define HH  64
#define NN  4096
#define SS  110
#define SP  128     // padded S

// ---------------- scratch (device globals) ----------------
__device__ __nv_bfloat16 g_yTh[(long long)BB * NN * CC];       // y transposed bf16 hi [B,N,C]
__device__ __nv_bfloat16 g_yTl[(long long)BB * NN * CC];
__device__ __nv_bfloat16 g_xTh[(long long)BB * NN * CC];
__device__ __nv_bfloat16 g_xTl[(long long)BB * NN * CC];
__device__ __nv_bfloat16 g_wh[CC * CC];                        // [theta;g] weights [m,k]
__device__ __nv_bfloat16 g_wl[CC * CC];
__device__ __nv_bfloat16 g_wphiTh[CC * ICN];                   // w_phi^T [c, ic]
__device__ __nv_bfloat16 g_wphiTl[CC * ICN];
__device__ __nv_bfloat16 g_wmBh[CC * ICN];                     // w_mask [c, ic] (native)
__device__ __nv_bfloat16 g_wmBl[CC * ICN];
__device__ unsigned      g_sppI[BB * SP * CC];                 // SPP maxes, order-mapped uint
__device__ __nv_bfloat16 g_sppTh[BB * SP * CC];                // spp^T bf16 [B, s(pad), ch]
__device__ __nv_bfloat16 g_sppTl[BB * SP * CC];
__device__ __nv_bfloat16 g_kkh[BB * SP * CC];                  // kk bf16 hi/lo [B, s, c]
__device__ __nv_bfloat16 g_kkl[BB * SP * CC];
__device__ float         g_v[BB * SP * CC];                    // v fp32 [B, s, c]
__device__ __nv_bfloat16 g_vTh[BB * CC * SP];                  // v^T bf16 [B, c, s]
__device__ __nv_bfloat16 g_vTl[BB * CC * SP];
__device__ float         g_logits[(long long)BB * SP * NN];    // [B, s(pad), n]
__device__ __nv_bfloat16 g_PTh[(long long)BB * NN * SP];       // exp(logits)^T [B, n, s]
__device__ __nv_bfloat16 g_PTl[(long long)BB * NN * SP];
__device__ float         g_max[BB * SS];
__device__ float         g_invsum[BB * SS];

// ---------------- helpers ----------------
__device__ __forceinline__ uint32_t smem_u32(const void* p) {
    uint32_t a;
    asm("{ .reg .u64 t; cvta.to.shared.u64 t, %1; cvt.u32.u64 %0, t; }" : "=r"(a) : "l"(p));
    return a;
}
// order-preserving float -> uint mapping (monotone under unsigned compare)
__device__ __forceinline__ unsigned mapf(float f) {
    unsigned u = __float_as_uint(f);
    return (u & 0x80000000u) ? ~u : (u | 0x80000000u);
}
__device__ __forceinline__ float unmapf(unsigned m) {
    unsigned b = (m & 0x80000000u) ? (m ^ 0x80000000u) : ~m;
    return __uint_as_float(b);
}

#define CP_ASYNC16(saddr, gaddr) \
    asm volatile("cp.async.cg.shared.global [%0], [%1], 16;" :: "r"(saddr), "l"(gaddr))
#define CP_COMMIT() asm volatile("cp.async.commit_group;")
#define CP_WAIT0()  asm volatile("cp.async.wait_group 0;")

#define LDSM4(r0, r1, r2, r3, addr) \
    asm volatile("ldmatrix.sync.aligned.m8n8.x4.shared.b16 {%0,%1,%2,%3}, [%4];" \
                 : "=r"(r0), "=r"(r1), "=r"(r2), "=r"(r3) : "r"(addr))

#define MMA16816(d, a, b) \
    asm volatile("mma.sync.aligned.m16n8k16.row.col.f32.bf16.bf16.f32 " \
                 "{%0,%1,%2,%3}, {%4,%5,%6,%7}, {%8,%9}, {%0,%1,%2,%3};" \
                 : "+f"((d)[0]), "+f"((d)[1]), "+f"((d)[2]), "+f"((d)[3]) \
                 : "r"((a)[0]), "r"((a)[1]), "r"((a)[2]), "r"((a)[3]), \
                   "r"((b)[0]), "r"((b)[1]))

// ---------------- bf16x3 mma.sync GEMM ----------------
// C[m,n] = sum_k A[m,k]*B[n,k]  (both [rows, K] K-contiguous, bf16 hi/lo)
// BM=BN=128, BK=32, 8 warps (2x4, warp tile 64x32), padded smem rows (K32+8).
// 2-stage cp.async double buffer, one barrier per k-tile. 2 CTAs/SM.
// OUTBF=1: write bf16 hi/lo pairs (Ch/Cl). SPPOUT=1: don't write C at all;
// reduce fragments into SPP pyramid maxes (order-mapped uint atomics).
#define LDP       40                 // padded row length (elements)
#define TILE_B    (128 * LDP * 2)    // 10240 bytes per operand tile
#define STAGE_B   (4 * TILE_B)       // Ah, Al, Bh, Bl
#define GSMEM_BYTES (2 * STAGE_B)    // 81920

template <int ADD, int OUTBF, int SPPOUT>
__global__ void __launch_bounds__(256, 2)
gemm_mma(const __nv_bfloat16* __restrict__ Ah, const __nv_bfloat16* __restrict__ Al,
         long long sA, int lda,
         const __nv_bfloat16* __restrict__ Bh, const __nv_bfloat16* __restrict__ Bl,
         long long sB, int ldb,
         float* __restrict__ C,
         __nv_bfloat16* __restrict__ Ch, __nv_bfloat16* __restrict__ Cl,
         long long sC, int ldc,
         const float* __restrict__ Cadd, long long sAdd, int K,
         unsigned* __restrict__ sppI)
{
    extern __shared__ char smem_raw[];
    const uint32_t sb = smem_u32(smem_raw);
    const int tid = threadIdx.x, wid = tid >> 5, lane = tid & 31;
    const int wm = wid & 1, wn = wid >> 1;       // 2 x 4 warp grid
    const int b = blockIdx.z;
    const int bm = blockIdx.y * 128, bn = blockIdx.x * 128;
    Ah += b * sA; Al += b * sA; Bh += b * sB; Bl += b * sB;
    if (OUTBF) { Ch += b * sC; Cl += b * sC; } else { C += b * sC; }
    if (ADD) Cadd += b * sAdd;

    const int nkt = K >> 5;

    // cp.async loader for one k-tile into stage buffer
    auto load_stage = [&](int kt, int buf) {
        const uint32_t stg = sb + buf * STAGE_B;
        const int k0 = kt << 5;
#pragma unroll
        for (int i = 0; i < 2; i++) {
            int id = tid + (i << 8);             // 0..511
            int row = id >> 2, cq = (id & 3) << 3;   // cq in elements (8 each)
            uint32_t soff = row * (LDP * 2) + (cq << 1);
            CP_ASYNC16(stg + 0 * TILE_B + soff, (const char*)(Ah + (long long)(bm + row) * lda + k0 + cq));
            CP_ASYNC16(stg + 1 * TILE_B + soff, (const char*)(Al + (long long)(bm + row) * lda + k0 + cq));
            CP_ASYNC16(stg + 2 * TILE_B + soff, (const char*)(Bh + (long long)(bn + row) * ldb + k0 + cq));
            CP_ASYNC16(stg + 3 * TILE_B + soff, (const char*)(Bl + (long long)(bn + row) * ldb + k0 + cq));
        }
    };

    float acc[4][4][4];
#pragma unroll
    for (int mi = 0; mi < 4; mi++)
#pragma unroll
        for (int ni = 0; ni < 4; ni++)
#pragma unroll
            for (int r = 0; r < 4; r++) acc[mi][ni][r] = 0.f;

    // per-lane ldmatrix byte offsets within an operand tile
    const uint32_t a_lb = (wm * 64 + (lane & 15)) * (LDP * 2) + ((lane >> 4) << 4);
    const uint32_t b_lb = (wn * 32 + (lane & 7) + ((lane >> 4) << 3)) * (LDP * 2)
                        + (((lane >> 3) & 1) << 4);

    load_stage(0, 0); CP_COMMIT();

    for (int kt = 0; kt < nkt; kt++) {
        const int buf = kt & 1;
        CP_WAIT0();                      // tile kt resident
        __syncthreads();                 // all warps done with compute(kt-1)
        if (kt + 1 < nkt) {              // prefetch overwrites buffer of kt-1
            load_stage(kt + 1, buf ^ 1); CP_COMMIT();
        }

        const uint32_t stg = sb + buf * STAGE_B;
#pragma unroll
        for (int k16 = 0; k16 < 2; k16++) {
            const uint32_t kb = k16 << 5;        // 16 elements = 32 bytes
            uint32_t bh[4][2], bl[4][2];
#pragma unroll
            for (int p = 0; p < 2; p++) {
                uint32_t bd = stg + 2 * TILE_B + b_lb + p * 16 * (LDP * 2) + kb;
                LDSM4(bh[2 * p][0], bh[2 * p][1], bh[2 * p + 1][0], bh[2 * p + 1][1], bd);
                LDSM4(bl[2 * p][0], bl[2 * p][1], bl[2 * p + 1][0], bl[2 * p + 1][1], bd + TILE_B);
            }
#pragma unroll
            for (int h = 0; h < 2; h++) {
                uint32_t ah[2][4], al[2][4];
#pragma unroll
                for (int m2 = 0; m2 < 2; m2++) {
                    uint32_t ad = stg + a_lb + (h * 2 + m2) * 16 * (LDP * 2) + kb;
                    LDSM4(ah[m2][0], ah[m2][1], ah[m2][2], ah[m2][3], ad);
                    LDSM4(al[m2][0], al[m2][1], al[m2][2], al[m2][3], ad + TILE_B);
                }
#pragma unroll
                for (int m2 = 0; m2 < 2; m2++)
#pragma unroll
                    for (int ni = 0; ni < 4; ni++)
                        MMA16816(acc[h * 2 + m2][ni], ah[m2], bh[ni]);
#pragma unroll
                for (int m2 = 0; m2 < 2; m2++)
#pragma unroll
                    for (int ni = 0; ni < 4; ni++)
                        MMA16816(acc[h * 2 + m2][ni], ah[m2], bl[ni]);
#pragma unroll
                for (int m2 = 0; m2 < 2; m2++)
#pragma unroll
                    for (int ni = 0; ni < 4; ni++)
                        MMA16816(acc[h * 2 + m2][ni], al[m2], bh[ni]);
            }
        }
    }

    if (SPPOUT) {
        // ---- fused SPP epilogue: CTA covers 128 channels x 2 image rows ----
        __syncthreads();                       // mainloop fully done; reuse smem
        unsigned* sm = reinterpret_cast<unsigned*>(smem_raw);   // [128 ch][2 r][18 lb]
        for (int i = tid; i < 128 * 36; i += 256) sm[i] = 0u;
        __syncthreads();
        const int ir0 = blockIdx.x * 2;
#pragma unroll
        for (int mi = 0; mi < 4; mi++)
#pragma unroll
            for (int ni = 0; ni < 4; ni++)
#pragma unroll
                for (int r = 0; r < 4; r++) {
                    unsigned mv = mapf(acc[mi][ni][r]);
                    int mloc = wm * 64 + mi * 16 + (lane >> 2) + ((r >> 1) << 3);
                    int colL = wn * 32 + ni * 8 + ((lane & 3) << 1) + (r & 1);
                    int r2 = colL >> 6, ic = colL & 63;
                    unsigned* row = sm + mloc * 36 + r2 * 18;
                    atomicMax(row + 10 + (ic >> 3), mv);              // o=8 (no overlap)
                    int c6 = (ic * 6) >> 6;                            // o=6
                    atomicMax(row + 4 + c6, mv);
                    if (c6 < 5 && ic >= (((c6 + 1) << 6) / 6)) atomicMax(row + 5 + c6, mv);
                    int c3 = (ic * 3) >> 6;                            // o=3
                    atomicMax(row + 1 + c3, mv);
                    if (c3 < 2 && ic >= (((c3 + 1) << 6) / 3)) atomicMax(row + 2 + c3, mv);
                    atomicMax(row + 0, mv);                            // o=1
                }
        __syncthreads();
        for (int i = tid; i < 128 * 36; i += 256) {
            int ch = i / 36, rem = i - ch * 36;
            int r2 = rem / 18, lb = rem - r2 * 18;
            unsigned v = sm[i];
            int ir = ir0 + r2;
            int o, cb, sbase;
            if (lb == 0)       { o = 1; cb = 0;       sbase = 0; }
            else if (lb < 4)   { o = 3; cb = lb - 1;  sbase = 1; }
            else if (lb < 10)  { o = 6; cb = lb - 4;  sbase = 10; }
            else               { o = 8; cb = lb - 10; sbase = 46; }
            int rb = (ir * o) >> 6;
            atomicMax(&sppI[((long long)(b * SP) + sbase + rb * o + cb) * CC + bm + ch], v);
            if (rb + 1 < o && ir >= (((rb + 1) << 6) / o))
                atomicMax(&sppI[((long long)(b * SP) + sbase + (rb + 1) * o + cb) * CC + bm + ch], v);
        }
        return;
    }

    // epilogue: fragment layout row = lane/4 (+8), col = 2*(lane%4)
#pragma unroll
    for (int mi = 0; mi < 4; mi++) {
#pragma unroll
        for (int ni = 0; ni < 4; ni++) {
            int r0 = bm + wm * 64 + mi * 16 + (lane >> 2);
            int col = bn + wn * 32 + ni * 8 + ((lane & 3) << 1);
            float2 v01 = make_float2(acc[mi][ni][0], acc[mi][ni][1]);
            float2 v23 = make_float2(acc[mi][ni][2], acc[mi][ni][3]);
            if (OUTBF) {
                __nv_bfloat16 h0 = __float2bfloat16(v01.x), h1 = __float2bfloat16(v01.y);
                __nv_bfloat16 h2 = __float2bfloat16(v23.x), h3 = __float2bfloat16(v23.y);
                __nv_bfloat162 p0; p0.x = h0; p0.y = h1;
                __nv_bfloat162 p1; p1.x = h2; p1.y = h3;
                *reinterpret_cast<__nv_bfloat162*>(Ch + (long long)r0 * ldc + col) = p0;
                *reinterpret_cast<__nv_bfloat162*>(Ch + (long long)(r0 + 8) * ldc + col) = p1;
                __nv_bfloat162 q0, q1;
                q0.x = __float2bfloat16(v01.x - __bfloat162float(h0));
                q0.y = __float2bfloat16(v01.y - __bfloat162float(h1));
                q1.x = __float2bfloat16(v23.x - __bfloat162float(h2));
                q1.y = __float2bfloat16(v23.y - __bfloat162float(h3));
                *reinterpret_cast<__nv_bfloat162*>(Cl + (long long)r0 * ldc + col) = q0;
                *reinterpret_cast<__nv_bfloat162*>(Cl + (long long)(r0 + 8) * ldc + col) = q1;
            } else {
                if (ADD) {
                    float2 a0 = *reinterpret_cast<const float2*>(Cadd + (long long)r0 * ldc + col);
                    float2 a1 = *reinterpret_cast<const float2*>(Cadd + (long long)(r0 + 8) * ldc + col);
                    v01.x += a0.x; v01.y += a0.y;
                    v23.x += a1.x; v23.y += a1.y;
                }
                *reinterpret_cast<float2*>(C + (long long)r0 * ldc + col) = v01;
                *reinterpret_cast<float2*>(C + (long long)(r0 + 8) * ldc + col) = v23;
            }
        }
    }
}

// ---------------- weight pack ----------------
__global__ void pack_kernel(const float* __restrict__ wth, const float* __restrict__ wg,
                            const float* __restrict__ wphi, const float* __restrict__ wmask) {
    int idx = blockIdx.x * 256 + threadIdx.x;
    if (idx < CC * CC) {
        int m = idx / CC, k = idx % CC;
        float w = (m < ICN) ? wth[m * CC + k] : wg[(m - ICN) * CC + k];
        __nv_bfloat16 h = __float2bfloat16(w);
        g_wh[idx] = h;
        g_wl[idx] = __float2bfloat16(w - __bfloat162float(h));
    }
    if (idx < CC * ICN) {
        int c = idx / ICN, ic = idx % ICN;
        float wp = wphi[ic * CC + c];
        __nv_bfloat16 h = __float2bfloat16(wp);
        g_wphiTh[idx] = h;
        g_wphiTl[idx] = __float2bfloat16(wp - __bfloat162float(h));
        float wm = wmask[idx];            // wmask is [c, ic] row-major already
        __nv_bfloat16 hm = __float2bfloat16(wm);
        g_wmBh[idx] = hm;
        g_wmBl[idx] = __float2bfloat16(wm - __bfloat162float(hm));
    }
}

// ---------------- SPP int-mapped -> bf16 hi/lo (+ zero pad rows) ----------
__global__ void sppcvt_kernel() {
    int gid = blockIdx.x * 256 + threadIdx.x;
    if (gid >= BB * SP * CC) return;
    int s = (gid / CC) & (SP - 1);
    float f = 0.f;
    if (s < SS) f = unmapf(g_sppI[gid]);
    __nv_bfloat16 h = __float2bfloat16(f);
    g_sppTh[gid] = h;
    g_sppTl[gid] = __float2bfloat16(f - __bfloat162float(h));
}

// ---------------- fp32 [C, N] -> bf16 hi/lo [N, C] (transpose-convert) ----
__global__ void tconv_kernel(const float* __restrict__ src,
                             __nv_bfloat16* __restrict__ dh, __nv_bfloat16* __restrict__ dl) {
    __shared__ float sm[32][33];
    int n0 = blockIdx.x * 32, c0 = blockIdx.y * 32, b = blockIdx.z;
    int tx = threadIdx.x, ty = threadIdx.y;
    src += (long long)b * CC * NN;
#pragma unroll
    for (int r = 0; r < 4; r++)
        sm[ty + 8 * r][tx] = src[(long long)(c0 + ty + 8 * r) * NN + n0 + tx];
    __syncthreads();
#pragma unroll
    for (int r = 0; r < 4; r++) {
        int n = n0 + ty + 8 * r, c = c0 + tx;
        float v = sm[tx][ty + 8 * r];
        __nv_bfloat16 h = __float2bfloat16(v);
        long long o = ((long long)b * NN + n) * CC + c;
        dh[o] = h;
        dl[o] = __float2bfloat16(v - __bfloat162float(h));
    }
}

// ---------------- row stats: max + 1/sum(exp) per (b,s) ----------------
__global__ void rowstat_kernel() {
    int s = blockIdx.x, b = blockIdx.y;
    const float* row = g_logits + ((long long)(b * SP + s)) * NN;
    __shared__ float t[NN];
    __shared__ float red[256];
    int tid = threadIdx.x;
    float mx = -INFINITY;
    for (int i = tid; i < NN; i += 256) {
        float v = row[i];
        t[i] = v;
        mx = fmaxf(mx, v);
    }
    red[tid] = mx;
    __syncthreads();
    for (int st = 128; st > 0; st >>= 1) {
        if (tid < st) red[tid] = fmaxf(red[tid], red[tid + st]);
        __syncthreads();
    }
    mx = red[0];
    __syncthreads();
    float sum = 0.f;
    for (int i = tid; i < NN; i += 256) sum += __expf(t[i] - mx);
    red[tid] = sum;
    __syncthreads();
    for (int st = 128; st > 0; st >>= 1) {
        if (tid < st) red[tid] += red[tid + st];
        __syncthreads();
    }
    if (tid == 0) {
        g_max[b * SS + s] = mx;
        g_invsum[b * SS + s] = 1.0f / red[0];
    }
}

// ---------------- exp + transpose: logits [s,n] -> PT bf16 [n,s] ----------
__global__ void texp_kernel() {
    __shared__ float sm[32][SP + 1];
    __shared__ float gmx[SP];
    int b = blockIdx.y, n0 = blockIdx.x * 32;
    int tid = threadIdx.x;
    if (tid < SS) gmx[tid] = g_max[b * SS + tid];
    __syncthreads();
    int tx = tid & 31, ty = tid >> 5;          // ty 0..7
#pragma unroll
    for (int r = 0; r < 16; r++) {
        int s = ty + (r << 3);
        float e = 0.f;
        if (s < SS)
            e = __expf(g_logits[((long long)(b * SP + s)) * NN + n0 + tx] - gmx[s]);
        sm[tx][s] = e;
    }
    __syncthreads();
#pragma unroll
    for (int w = 0; w < 16; w++) {
        int idx = tid + (w << 8);
        int nl = idx >> 7, s = idx & 127;
        float v = sm[nl][s];
        __nv_bfloat16 h = __float2bfloat16(v);
        long long o = ((long long)(b * NN) + n0 + nl) * SP + s;
        g_PTh[o] = h;
        g_PTl[o] = __float2bfloat16(v - __bfloat162float(h));
    }
}

// ---------------- v [s,c] * invsum -> vT bf16 hi/lo [c,s] ----------------
__global__ void vt_kernel() {
    int gid = blockIdx.x * 256 + threadIdx.x;
    if (gid >= BB * CC * SP) return;
    int b = gid >> 16;                // CC*SP = 65536
    int rem = gid & 65535;
    int c = rem >> 7, s = rem & 127;
    float val = 0.f;
    if (s < SS)
        val = g_v[((long long)(b * SP + s)) * CC + c] * g_invsum[b * SS + s];
    __nv_bfloat16 h = __float2bfloat16(val);
    long long o = ((long long)b * CC + c) * SP + s;
    g_vTh[o] = h;
    g_vTl[o] = __float2bfloat16(val - __bfloat162float(h));
}

// ---------------- launch ----------------
extern "C" void kernel_launch(void* const* d_in, const int* in_sizes, int n_in,
                              void* d_out, int out_size) {
    const float* x     = (const float*)d_in[0];
    const float* y     = (const float*)d_in[1];
    const float* wphi  = (const float*)d_in[2];
    const float* wth   = (const float*)d_in[3];
    const float* wg    = (const float*)d_in[4];
    const float* wmask = (const float*)d_in[5];
    float* out = (float*)d_out;

    // one-time resources (host-side; not captured operations)
    static cudaStream_t s1 = nullptr, s2 = nullptr;
    static cudaEvent_t ev0, ev1, evSpp, evRow, ev3;
    if (!s1) {
        cudaStreamCreateWithFlags(&s1, cudaStreamNonBlocking);
        cudaStreamCreateWithFlags(&s2, cudaStreamNonBlocking);
        cudaEventCreateWithFlags(&ev0,   cudaEventDisableTiming);
        cudaEventCreateWithFlags(&ev1,   cudaEventDisableTiming);
        cudaEventCreateWithFlags(&evSpp, cudaEventDisableTiming);
        cudaEventCreateWithFlags(&evRow, cudaEventDisableTiming);
        cudaEventCreateWithFlags(&ev3,   cudaEventDisableTiming);
        cudaFuncSetAttribute(gemm_mma<0,0,0>, cudaFuncAttributeMaxDynamicSharedMemorySize, GSMEM_BYTES);
        cudaFuncSetAttribute(gemm_mma<1,0,0>, cudaFuncAttributeMaxDynamicSharedMemorySize, GSMEM_BYTES);
        cudaFuncSetAttribute(gemm_mma<0,1,0>, cudaFuncAttributeMaxDynamicSharedMemorySize, GSMEM_BYTES);
        cudaFuncSetAttribute(gemm_mma<0,0,1>, cudaFuncAttributeMaxDynamicSharedMemorySize, GSMEM_BYTES);
    }

    float *v, *logits;
    __nv_bfloat16 *yTh, *yTl, *xTh, *xTl, *wh, *wl, *wpTh, *wpTl, *wmBh, *wmBl;
    __nv_bfloat16 *spTh, *spTl, *kkh, *kkl, *vTh, *vTl, *PTh, *PTl;
    unsigned* sppI;
    cudaGetSymbolAddress((void**)&v, g_v);
    cudaGetSymbolAddress((void**)&logits, g_logits);
    cudaGetSymbolAddress((void**)&sppI, g_sppI);
    cudaGetSymbolAddress((void**)&yTh, g_yTh);   cudaGetSymbolAddress((void**)&yTl, g_yTl);
    cudaGetSymbolAddress((void**)&xTh, g_xTh);   cudaGetSymbolAddress((void**)&xTl, g_xTl);
    cudaGetSymbolAddress((void**)&wh, g_wh);     cudaGetSymbolAddress((void**)&wl, g_wl);
    cudaGetSymbolAddress((void**)&wpTh, g_wphiTh); cudaGetSymbolAddress((void**)&wpTl, g_wphiTl);
    cudaGetSymbolAddress((void**)&wmBh, g_wmBh); cudaGetSymbolAddress((void**)&wmBl, g_wmBl);
    cudaGetSymbolAddress((void**)&spTh, g_sppTh); cudaGetSymbolAddress((void**)&spTl, g_sppTl);
    cudaGetSymbolAddress((void**)&kkh, g_kkh);   cudaGetSymbolAddress((void**)&kkl, g_kkl);
    cudaGetSymbolAddress((void**)&vTh, g_vTh);   cudaGetSymbolAddress((void**)&vTl, g_vTl);
    cudaGetSymbolAddress((void**)&PTh, g_PTh);   cudaGetSymbolAddress((void**)&PTl, g_PTl);

    // ---- fork: tconv_x on s1 (depends only on input x) ----
    cudaEventRecord(ev0, 0);
    cudaStreamWaitEvent(s1, ev0, 0);
    tconv_kernel<<<dim3(NN / 32, CC / 32, BB), dim3(32, 8), 0, s1>>>(x, xTh, xTl);
    cudaEventRecord(ev1, s1);

    // ---- main chain on default stream ----
    cudaMemsetAsync(sppI, 0, sizeof(unsigned) * BB * SP * CC, 0);
    pack_kernel<<<(CC * CC + 255) / 256, 256>>>(wth, wg, wphi, wmask);
    tconv_kernel<<<dim3(NN / 32, CC / 32, BB), dim3(32, 8)>>>(y, yTh, yTl);

    // conv GEMM with fused SPP epilogue (M=512, N=4096, K=512)
    gemm_mma<0,0,1><<<dim3(NN / 128, CC / 128, BB), 256, GSMEM_BYTES>>>(
        wh, wl, 0LL, CC, yTh, yTl, (long long)NN * CC, CC,
        nullptr, nullptr, nullptr, 0LL, NN, nullptr, 0LL, CC, sppI);

    // int-mapped maxes -> bf16 hi/lo (+ pad zero)
    sppcvt_kernel<<<(BB * SP * CC + 255) / 256, 256>>>();

    // ---- fork: v chain on s2 (needs pack + sppcvt) ----
    cudaEventRecord(evSpp, 0);
    cudaStreamWaitEvent(s2, evSpp, 0);
    gemm_mma<0,0,0><<<dim3(CC / 128, 1, BB), 256, GSMEM_BYTES, s2>>>(
        spTh + ICN, spTl + ICN, (long long)SP * CC, CC, wmBh, wmBl, 0LL, ICN,
        v, nullptr, nullptr, (long long)SP * CC, CC, nullptr, 0LL, ICN, nullptr);

    // kk GEMM with fused bf16 hi/lo output  (M=128, N=512, K=256)
    gemm_mma<0,1,0><<<dim3(CC / 128, 1, BB), 256, GSMEM_BYTES>>>(
        spTh, spTl, (long long)SP * CC, CC, wpTh, wpTl, 0LL, ICN,
        nullptr, kkh, kkl, (long long)SP * CC, CC, nullptr, 0LL, ICN, nullptr);

    // join: logits GEMM needs xT
    cudaStreamWaitEvent(0, ev1, 0);
    gemm_mma<0,0,0><<<dim3(NN / 128, 1, BB), 256, GSMEM_BYTES>>>(
        kkh, kkl, (long long)SP * CC, CC, xTh, xTl, (long long)NN * CC, CC,
        logits, nullptr, nullptr, (long long)SP * NN, NN, nullptr, 0LL, CC, nullptr);

    rowstat_kernel<<<dim3(SS, BB), 256>>>();

    // ---- fork: vt on s2 (needs vGEMM [s2 order] + rowstat invsum) ----
    cudaEventRecord(evRow, 0);
    cudaStreamWaitEvent(s2, evRow, 0);
    vt_kernel<<<(BB * CC * SP + 255) / 256, 256, 0, s2>>>();
    cudaEventRecord(ev3, s2);

    texp_kernel<<<dim3(NN / 32, BB), 256>>>();

    // join: output GEMM needs vT + PT
    cudaStreamWaitEvent(0, ev3, 0);
    gemm_mma<1,0,0><<<dim3(NN / 128, CC / 128, BB), 256, GSMEM_BYTES>>>(
        vTh, vTl, (long long)CC * SP, SP, PTh, PTl, (long long)NN * SP, SP,
        out, nullptr, nullptr, (long long)CC * NN, NN, x, (long long)CC * NN, SP, nullptr);
}

// round 13
// speedup vs baseline: 1.2932x; 1.1018x over previous
#include <cuda_runtime.h>
#include <cuda_bf16.h>
#include <math.h>
#include <stdint.h>

// ---------------- problem constants ----------------
#define BB  16
#define CC  512
#define ICN 256
#define HH  64
#define NN  4096
#define SS  110
#define SP  128     // padded S

// ---------------- scratch (device globals) ----------------
__device__ __nv_bfloat16 g_yTh[(long long)BB * NN * CC];       // y transposed bf16 hi [B,N,C]
__device__ __nv_bfloat16 g_yTl[(long long)BB * NN * CC];
__device__ __nv_bfloat16 g_xTh[(long long)BB * NN * CC];
__device__ __nv_bfloat16 g_xTl[(long long)BB * NN * CC];
__device__ __nv_bfloat16 g_wh[CC * CC];                        // [theta;g] weights [m,k]
__device__ __nv_bfloat16 g_wl[CC * CC];
__device__ __nv_bfloat16 g_wphiTh[CC * ICN];                   // w_phi^T [c, ic]
__device__ __nv_bfloat16 g_wphiTl[CC * ICN];
__device__ __nv_bfloat16 g_wmBh[CC * ICN];                     // w_mask [c, ic] (native)
__device__ __nv_bfloat16 g_wmBl[CC * ICN];
__device__ unsigned      g_sppI[BB * SP * CC];                 // SPP maxes, order-mapped uint
__device__ __nv_bfloat16 g_sppTh[BB * SP * CC];                // spp^T bf16 [B, s(pad), ch]
__device__ __nv_bfloat16 g_sppTl[BB * SP * CC];
__device__ __nv_bfloat16 g_kkh[BB * SP * CC];                  // kk bf16 hi/lo [B, s, c]
__device__ __nv_bfloat16 g_kkl[BB * SP * CC];
__device__ float         g_v[BB * SP * CC];                    // v fp32 [B, s, c]
__device__ __nv_bfloat16 g_vTh[BB * CC * SP];                  // v^T bf16 [B, c, s]
__device__ __nv_bfloat16 g_vTl[BB * CC * SP];
__device__ float         g_logits[(long long)BB * SP * NN];    // [B, s(pad), n]
__device__ __nv_bfloat16 g_PTh[(long long)BB * NN * SP];       // exp(logits)^T [B, n, s]
__device__ __nv_bfloat16 g_PTl[(long long)BB * NN * SP];
__device__ float         g_max[BB * SS];
__device__ float         g_invsum[BB * SS];

// ---------------- helpers ----------------
__device__ __forceinline__ uint32_t smem_u32(const void* p) {
    uint32_t a;
    asm("{ .reg .u64 t; cvta.to.shared.u64 t, %1; cvt.u32.u64 %0, t; }" : "=r"(a) : "l"(p));
    return a;
}
// order-preserving float -> uint mapping (monotone under unsigned compare)
__device__ __forceinline__ unsigned mapf(float f) {
    unsigned u = __float_as_uint(f);
    return (u & 0x80000000u) ? ~u : (u | 0x80000000u);
}
__device__ __forceinline__ float unmapf(unsigned m) {
    unsigned b = (m & 0x80000000u) ? (m ^ 0x80000000u) : ~m;
    return __uint_as_float(b);
}

#define CP_ASYNC16(saddr, gaddr) \
    asm volatile("cp.async.cg.shared.global [%0], [%1], 16;" :: "r"(saddr), "l"(gaddr))
#define CP_COMMIT() asm volatile("cp.async.commit_group;")
#define CP_WAIT0()  asm volatile("cp.async.wait_group 0;")

#define LDSM4(r0, r1, r2, r3, addr) \
    asm volatile("ldmatrix.sync.aligned.m8n8.x4.shared.b16 {%0,%1,%2,%3}, [%4];" \
                 : "=r"(r0), "=r"(r1), "=r"(r2), "=r"(r3) : "r"(addr))

#define MMA16816(d, a, b) \
    asm volatile("mma.sync.aligned.m16n8k16.row.col.f32.bf16.bf16.f32 " \
                 "{%0,%1,%2,%3}, {%4,%5,%6,%7}, {%8,%9}, {%0,%1,%2,%3};" \
                 : "+f"((d)[0]), "+f"((d)[1]), "+f"((d)[2]), "+f"((d)[3]) \
                 : "r"((a)[0]), "r"((a)[1]), "r"((a)[2]), "r"((a)[3]), \
                   "r"((b)[0]), "r"((b)[1]))

// ---------------- bf16x3 mma.sync GEMM ----------------
// C[m,n] = sum_k A[m,k]*B[n,k]  (both [rows, K] K-contiguous, bf16 hi/lo)
// BM=BN=128, BK=32, 8 warps (2x4, warp tile 64x32), padded smem rows (K32+8).
// 2-stage cp.async double buffer, one barrier per k-tile. 2 CTAs/SM.
// OUTBF=1: write bf16 hi/lo pairs (Ch/Cl). SPPOUT=1: don't write C at all;
// reduce fragments into SPP pyramid maxes. Phase 1 keeps only o=6 + o=8
// column bins (o=3/o=1 are exact unions of o=6 bins, derived in phase 2);
// o=8 is fully shuffle-reduced, o=6 pairwise-max'd with exact boundaries.
#define LDP       40                 // padded row length (elements)
#define TILE_B    (128 * LDP * 2)    // 10240 bytes per operand tile
#define STAGE_B   (4 * TILE_B)       // Ah, Al, Bh, Bl
#define GSMEM_BYTES (2 * STAGE_B)    // 81920

template <int ADD, int OUTBF, int SPPOUT>
__global__ void __launch_bounds__(256, 2)
gemm_mma(const __nv_bfloat16* __restrict__ Ah, const __nv_bfloat16* __restrict__ Al,
         long long sA, int lda,
         const __nv_bfloat16* __restrict__ Bh, const __nv_bfloat16* __restrict__ Bl,
         long long sB, int ldb,
         float* __restrict__ C,
         __nv_bfloat16* __restrict__ Ch, __nv_bfloat16* __restrict__ Cl,
         long long sC, int ldc,
         const float* __restrict__ Cadd, long long sAdd, int K,
         unsigned* __restrict__ sppI)
{
    extern __shared__ char smem_raw[];
    const uint32_t sb = smem_u32(smem_raw);
    const int tid = threadIdx.x, wid = tid >> 5, lane = tid & 31;
    const int wm = wid & 1, wn = wid >> 1;       // 2 x 4 warp grid
    const int b = blockIdx.z;
    const int bm = blockIdx.y * 128, bn = blockIdx.x * 128;
    Ah += b * sA; Al += b * sA; Bh += b * sB; Bl += b * sB;
    if (OUTBF) { Ch += b * sC; Cl += b * sC; } else { C += b * sC; }
    if (ADD) Cadd += b * sAdd;

    const int nkt = K >> 5;

    // cp.async loader for one k-tile into stage buffer
    auto load_stage = [&](int kt, int buf) {
        const uint32_t stg = sb + buf * STAGE_B;
        const int k0 = kt << 5;
#pragma unroll
        for (int i = 0; i < 2; i++) {
            int id = tid + (i << 8);             // 0..511
            int row = id >> 2, cq = (id & 3) << 3;   // cq in elements (8 each)
            uint32_t soff = row * (LDP * 2) + (cq << 1);
            CP_ASYNC16(stg + 0 * TILE_B + soff, (const char*)(Ah + (long long)(bm + row) * lda + k0 + cq));
            CP_ASYNC16(stg + 1 * TILE_B + soff, (const char*)(Al + (long long)(bm + row) * lda + k0 + cq));
            CP_ASYNC16(stg + 2 * TILE_B + soff, (const char*)(Bh + (long long)(bn + row) * ldb + k0 + cq));
            CP_ASYNC16(stg + 3 * TILE_B + soff, (const char*)(Bl + (long long)(bn + row) * ldb + k0 + cq));
        }
    };

    float acc[4][4][4];
#pragma unroll
    for (int mi = 0; mi < 4; mi++)
#pragma unroll
        for (int ni = 0; ni < 4; ni++)
#pragma unroll
            for (int r = 0; r < 4; r++) acc[mi][ni][r] = 0.f;

    // per-lane ldmatrix byte offsets within an operand tile
    const uint32_t a_lb = (wm * 64 + (lane & 15)) * (LDP * 2) + ((lane >> 4) << 4);
    const uint32_t b_lb = (wn * 32 + (lane & 7) + ((lane >> 4) << 3)) * (LDP * 2)
                        + (((lane >> 3) & 1) << 4);

    load_stage(0, 0); CP_COMMIT();

    for (int kt = 0; kt < nkt; kt++) {
        const int buf = kt & 1;
        CP_WAIT0();                      // tile kt resident
        __syncthreads();                 // all warps done with compute(kt-1)
        if (kt + 1 < nkt) {              // prefetch overwrites buffer of kt-1
            load_stage(kt + 1, buf ^ 1); CP_COMMIT();
        }

        const uint32_t stg = sb + buf * STAGE_B;
#pragma unroll
        for (int k16 = 0; k16 < 2; k16++) {
            const uint32_t kb = k16 << 5;        // 16 elements = 32 bytes
            uint32_t bh[4][2], bl[4][2];
#pragma unroll
            for (int p = 0; p < 2; p++) {
                uint32_t bd = stg + 2 * TILE_B + b_lb + p * 16 * (LDP * 2) + kb;
                LDSM4(bh[2 * p][0], bh[2 * p][1], bh[2 * p + 1][0], bh[2 * p + 1][1], bd);
                LDSM4(bl[2 * p][0], bl[2 * p][1], bl[2 * p + 1][0], bl[2 * p + 1][1], bd + TILE_B);
            }
#pragma unroll
            for (int h = 0; h < 2; h++) {
                uint32_t ah[2][4], al[2][4];
#pragma unroll
                for (int m2 = 0; m2 < 2; m2++) {
                    uint32_t ad = stg + a_lb + (h * 2 + m2) * 16 * (LDP * 2) + kb;
                    LDSM4(ah[m2][0], ah[m2][1], ah[m2][2], ah[m2][3], ad);
                    LDSM4(al[m2][0], al[m2][1], al[m2][2], al[m2][3], ad + TILE_B);
                }
#pragma unroll
                for (int m2 = 0; m2 < 2; m2++)
#pragma unroll
                    for (int ni = 0; ni < 4; ni++)
                        MMA16816(acc[h * 2 + m2][ni], ah[m2], bh[ni]);
#pragma unroll
                for (int m2 = 0; m2 < 2; m2++)
#pragma unroll
                    for (int ni = 0; ni < 4; ni++)
                        MMA16816(acc[h * 2 + m2][ni], ah[m2], bl[ni]);
#pragma unroll
                for (int m2 = 0; m2 < 2; m2++)
#pragma unroll
                    for (int ni = 0; ni < 4; ni++)
                        MMA16816(acc[h * 2 + m2][ni], al[m2], bh[ni]);
            }
        }
    }

    if (SPPOUT) {
        // ---- fused SPP epilogue (optimized): sm[128 ch][2 r][14 bins]
        //      bins 0-5: o=6 col bins; bins 6-13: o=8 col bins.
        __syncthreads();                       // mainloop fully done; reuse smem
        unsigned* sm = reinterpret_cast<unsigned*>(smem_raw);
        for (int i = tid; i < 128 * 2 * 14; i += 256) sm[i] = 0u;
        __syncthreads();
        const int r2 = wn >> 1;                        // image-row within CTA (uniform/warp)
#pragma unroll
        for (int mi = 0; mi < 4; mi++) {
#pragma unroll
            for (int rr = 0; rr < 2; rr++) {
                int mloc = wm * 64 + mi * 16 + (lane >> 2) + (rr << 3);
                unsigned* row = sm + (mloc * 2 + r2) * 14;
#pragma unroll
                for (int ni = 0; ni < 4; ni++) {
                    float v0 = acc[mi][ni][rr * 2 + 0];
                    float v1 = acc[mi][ni][rr * 2 + 1];
                    int e = ((wn & 1) << 5) + ni * 8 + ((lane & 3) << 1);  // even col 0..62
                    float pm = fmaxf(v0, v1);
                    // o=8: full octet max via 2 butterflies over lane&3
                    float m8 = pm;
                    m8 = fmaxf(m8, __shfl_xor_sync(0xffffffffu, m8, 1));
                    m8 = fmaxf(m8, __shfl_xor_sync(0xffffffffu, m8, 2));
                    if ((lane & 3) == 0) atomicMax(row + 6 + (e >> 3), mapf(m8));
                    // o=6: pairwise with exact PyTorch bin boundaries
                    int b0 = (e * 6) >> 6, b1 = ((e + 1) * 6) >> 6;
                    if (b0 == b1) {
                        atomicMax(row + b0, mapf(pm));
                        if (b0 < 5 && (e + 1) >= (((b0 + 1) << 6) / 6))
                            atomicMax(row + b0 + 1, mapf(v1));     // odd overlap col (21,53)
                    } else {
                        // e is an even overlap col (10 or 42): e in b0 & b1; e+1 in b1
                        atomicMax(row + b0, mapf(v0));
                        atomicMax(row + b1, mapf(pm));
                    }
                }
            }
        }
        __syncthreads();
        // phase 2: one thread per (ch, r2); derive o=3 / o=1 from o=6 unions
        {
            int ch = tid >> 1, rr2 = tid & 1;
            unsigned* row = sm + tid * 14;
            unsigned o6v[6], o8v[8];
#pragma unroll
            for (int i = 0; i < 6; i++) o6v[i] = row[i];
#pragma unroll
            for (int i = 0; i < 8; i++) o8v[i] = row[6 + i];
            unsigned o3v[3];
            o3v[0] = max(o6v[0], o6v[1]);
            o3v[1] = max(o6v[2], o6v[3]);
            o3v[2] = max(o6v[4], o6v[5]);
            unsigned o1v = max(o3v[0], max(o3v[1], o3v[2]));
            int ir = blockIdx.x * 2 + rr2;
            long long cbase = (long long)(b * SP) * CC;
            auto emit = [&](int o, int sbase, int cb, unsigned v) {
                int rb = (ir * o) >> 6;
                atomicMax(&sppI[cbase + (long long)(sbase + rb * o + cb) * CC + bm + ch], v);
                if (rb + 1 < o && ir >= (((rb + 1) << 6) / o))
                    atomicMax(&sppI[cbase + (long long)(sbase + (rb + 1) * o + cb) * CC + bm + ch], v);
            };
            emit(1, 0, 0, o1v);
#pragma unroll
            for (int cb = 0; cb < 3; cb++) emit(3, 1, cb, o3v[cb]);
#pragma unroll
            for (int cb = 0; cb < 6; cb++) emit(6, 10, cb, o6v[cb]);
#pragma unroll
            for (int cb = 0; cb < 8; cb++) emit(8, 46, cb, o8v[cb]);
        }
        return;
    }

    // epilogue: fragment layout row = lane/4 (+8), col = 2*(lane%4)
#pragma unroll
    for (int mi = 0; mi < 4; mi++) {
#pragma unroll
        for (int ni = 0; ni < 4; ni++) {
            int r0 = bm + wm * 64 + mi * 16 + (lane >> 2);
            int col = bn + wn * 32 + ni * 8 + ((lane & 3) << 1);
            float2 v01 = make_float2(acc[mi][ni][0], acc[mi][ni][1]);
            float2 v23 = make_float2(acc[mi][ni][2], acc[mi][ni][3]);
            if (OUTBF) {
                __nv_bfloat16 h0 = __float2bfloat16(v01.x), h1 = __float2bfloat16(v01.y);
                __nv_bfloat16 h2 = __float2bfloat16(v23.x), h3 = __float2bfloat16(v23.y);
                __nv_bfloat162 p0; p0.x = h0; p0.y = h1;
                __nv_bfloat162 p1; p1.x = h2; p1.y = h3;
                *reinterpret_cast<__nv_bfloat162*>(Ch + (long long)r0 * ldc + col) = p0;
                *reinterpret_cast<__nv_bfloat162*>(Ch + (long long)(r0 + 8) * ldc + col) = p1;
                __nv_bfloat162 q0, q1;
                q0.x = __float2bfloat16(v01.x - __bfloat162float(h0));
                q0.y = __float2bfloat16(v01.y - __bfloat162float(h1));
                q1.x = __float2bfloat16(v23.x - __bfloat162float(h2));
                q1.y = __float2bfloat16(v23.y - __bfloat162float(h3));
                *reinterpret_cast<__nv_bfloat162*>(Cl + (long long)r0 * ldc + col) = q0;
                *reinterpret_cast<__nv_bfloat162*>(Cl + (long long)(r0 + 8) * ldc + col) = q1;
            } else {
                if (ADD) {
                    float2 a0 = *reinterpret_cast<const float2*>(Cadd + (long long)r0 * ldc + col);
                    float2 a1 = *reinterpret_cast<const float2*>(Cadd + (long long)(r0 + 8) * ldc + col);
                    v01.x += a0.x; v01.y += a0.y;
                    v23.x += a1.x; v23.y += a1.y;
                }
                *reinterpret_cast<float2*>(C + (long long)r0 * ldc + col) = v01;
                *reinterpret_cast<float2*>(C + (long long)(r0 + 8) * ldc + col) = v23;
            }
        }
    }
}

// ---------------- weight pack ----------------
__global__ void pack_kernel(const float* __restrict__ wth, const float* __restrict__ wg,
                            const float* __restrict__ wphi, const float* __restrict__ wmask) {
    int idx = blockIdx.x * 256 + threadIdx.x;
    if (idx < CC * CC) {
        int m = idx / CC, k = idx % CC;
        float w = (m < ICN) ? wth[m * CC + k] : wg[(m - ICN) * CC + k];
        __nv_bfloat16 h = __float2bfloat16(w);
        g_wh[idx] = h;
        g_wl[idx] = __float2bfloat16(w - __bfloat162float(h));
    }
    if (idx < CC * ICN) {
        int c = idx / ICN, ic = idx % ICN;
        float wp = wphi[ic * CC + c];
        __nv_bfloat16 h = __float2bfloat16(wp);
        g_wphiTh[idx] = h;
        g_wphiTl[idx] = __float2bfloat16(wp - __bfloat162float(h));
        float wm = wmask[idx];            // wmask is [c, ic] row-major already
        __nv_bfloat16 hm = __float2bfloat16(wm);
        g_wmBh[idx] = hm;
        g_wmBl[idx] = __float2bfloat16(wm - __bfloat162float(hm));
    }
}

// ---------------- SPP int-mapped -> bf16 hi/lo (+ zero pad rows) ----------
__global__ void sppcvt_kernel() {
    int gid = blockIdx.x * 256 + threadIdx.x;
    if (gid >= BB * SP * CC) return;
    int s = (gid / CC) & (SP - 1);
    float f = 0.f;
    if (s < SS) f = unmapf(g_sppI[gid]);
    __nv_bfloat16 h = __float2bfloat16(f);
    g_sppTh[gid] = h;
    g_sppTl[gid] = __float2bfloat16(f - __bfloat162float(h));
}

// ---------------- fp32 [C, N] -> bf16 hi/lo [N, C] (transpose-convert) ----
__global__ void tconv_kernel(const float* __restrict__ src,
                             __nv_bfloat16* __restrict__ dh, __nv_bfloat16* __restrict__ dl) {
    __shared__ float sm[32][33];
    int n0 = blockIdx.x * 32, c0 = blockIdx.y * 32, b = blockIdx.z;
    int tx = threadIdx.x, ty = threadIdx.y;
    src += (long long)b * CC * NN;
#pragma unroll
    for (int r = 0; r < 4; r++)
        sm[ty + 8 * r][tx] = src[(long long)(c0 + ty + 8 * r) * NN + n0 + tx];
    __syncthreads();
#pragma unroll
    for (int r = 0; r < 4; r++) {
        int n = n0 + ty + 8 * r, c = c0 + tx;
        float v = sm[tx][ty + 8 * r];
        __nv_bfloat16 h = __float2bfloat16(v);
        long long o = ((long long)b * NN + n) * CC + c;
        dh[o] = h;
        dl[o] = __float2bfloat16(v - __bfloat162float(h));
    }
}

// ---------------- row stats: max + 1/sum(exp) per (b,s) ----------------
__global__ void rowstat_kernel() {
    int s = blockIdx.x, b = blockIdx.y;
    const float* row = g_logits + ((long long)(b * SP + s)) * NN;
    __shared__ float t[NN];
    __shared__ float red[256];
    int tid = threadIdx.x;
    float mx = -INFINITY;
    for (int i = tid; i < NN; i += 256) {
        float v = row[i];
        t[i] = v;
        mx = fmaxf(mx, v);
    }
    red[tid] = mx;
    __syncthreads();
    for (int st = 128; st > 0; st >>= 1) {
        if (tid < st) red[tid] = fmaxf(red[tid], red[tid + st]);
        __syncthreads();
    }
    mx = red[0];
    __syncthreads();
    float sum = 0.f;
    for (int i = tid; i < NN; i += 256) sum += __expf(t[i] - mx);
    red[tid] = sum;
    __syncthreads();
    for (int st = 128; st > 0; st >>= 1) {
        if (tid < st) red[tid] += red[tid + st];
        __syncthreads();
    }
    if (tid == 0) {
        g_max[b * SS + s] = mx;
        g_invsum[b * SS + s] = 1.0f / red[0];
    }
}

// ---------------- exp + transpose: logits [s,n] -> PT bf16 [n,s] ----------
__global__ void texp_kernel() {
    __shared__ float sm[32][SP + 1];
    __shared__ float gmx[SP];
    int b = blockIdx.y, n0 = blockIdx.x * 32;
    int tid = threadIdx.x;
    if (tid < SS) gmx[tid] = g_max[b * SS + tid];
    __syncthreads();
    int tx = tid & 31, ty = tid >> 5;          // ty 0..7
#pragma unroll
    for (int r = 0; r < 16; r++) {
        int s = ty + (r << 3);
        float e = 0.f;
        if (s < SS)
            e = __expf(g_logits[((long long)(b * SP + s)) * NN + n0 + tx] - gmx[s]);
        sm[tx][s] = e;
    }
    __syncthreads();
#pragma unroll
    for (int w = 0; w < 16; w++) {
        int idx = tid + (w << 8);
        int nl = idx >> 7, s = idx & 127;
        float v = sm[nl][s];
        __nv_bfloat16 h = __float2bfloat16(v);
        long long o = ((long long)(b * NN) + n0 + nl) * SP + s;
        g_PTh[o] = h;
        g_PTl[o] = __float2bfloat16(v - __bfloat162float(h));
    }
}

// ---------------- v [s,c] * invsum -> vT bf16 hi/lo [c,s] ----------------
__global__ void vt_kernel() {
    int gid = blockIdx.x * 256 + threadIdx.x;
    if (gid >= BB * CC * SP) return;
    int b = gid >> 16;                // CC*SP = 65536
    int rem = gid & 65535;
    int c = rem >> 7, s = rem & 127;
    float val = 0.f;
    if (s < SS)
        val = g_v[((long long)(b * SP + s)) * CC + c] * g_invsum[b * SS + s];
    __nv_bfloat16 h = __float2bfloat16(val);
    long long o = ((long long)b * CC + c) * SP + s;
    g_vTh[o] = h;
    g_vTl[o] = __float2bfloat16(val - __bfloat162float(h));
}

// ---------------- launch ----------------
extern "C" void kernel_launch(void* const* d_in, const int* in_sizes, int n_in,
                              void* d_out, int out_size) {
    const float* x     = (const float*)d_in[0];
    const float* y     = (const float*)d_in[1];
    const float* wphi  = (const float*)d_in[2];
    const float* wth   = (const float*)d_in[3];
    const float* wg    = (const float*)d_in[4];
    const float* wmask = (const float*)d_in[5];
    float* out = (float*)d_out;

    // one-time resources (host-side; not captured operations)
    static cudaStream_t s1 = nullptr, s2 = nullptr;
    static cudaEvent_t ev0, ev1, evSpp, evRow, ev3;
    if (!s1) {
        cudaStreamCreateWithFlags(&s1, cudaStreamNonBlocking);
        cudaStreamCreateWithFlags(&s2, cudaStreamNonBlocking);
        cudaEventCreateWithFlags(&ev0,   cudaEventDisableTiming);
        cudaEventCreateWithFlags(&ev1,   cudaEventDisableTiming);
        cudaEventCreateWithFlags(&evSpp, cudaEventDisableTiming);
        cudaEventCreateWithFlags(&evRow, cudaEventDisableTiming);
        cudaEventCreateWithFlags(&ev3,   cudaEventDisableTiming);
        cudaFuncSetAttribute(gemm_mma<0,0,0>, cudaFuncAttributeMaxDynamicSharedMemorySize, GSMEM_BYTES);
        cudaFuncSetAttribute(gemm_mma<1,0,0>, cudaFuncAttributeMaxDynamicSharedMemorySize, GSMEM_BYTES);
        cudaFuncSetAttribute(gemm_mma<0,1,0>, cudaFuncAttributeMaxDynamicSharedMemorySize, GSMEM_BYTES);
        cudaFuncSetAttribute(gemm_mma<0,0,1>, cudaFuncAttributeMaxDynamicSharedMemorySize, GSMEM_BYTES);
    }

    float *v, *logits;
    __nv_bfloat16 *yTh, *yTl, *xTh, *xTl, *wh, *wl, *wpTh, *wpTl, *wmBh, *wmBl;
    __nv_bfloat16 *spTh, *spTl, *kkh, *kkl, *vTh, *vTl, *PTh, *PTl;
    unsigned* sppI;
    cudaGetSymbolAddress((void**)&v, g_v);
    cudaGetSymbolAddress((void**)&logits, g_logits);
    cudaGetSymbolAddress((void**)&sppI, g_sppI);
    cudaGetSymbolAddress((void**)&yTh, g_yTh);   cudaGetSymbolAddress((void**)&yTl, g_yTl);
    cudaGetSymbolAddress((void**)&xTh, g_xTh);   cudaGetSymbolAddress((void**)&xTl, g_xTl);
    cudaGetSymbolAddress((void**)&wh, g_wh);     cudaGetSymbolAddress((void**)&wl, g_wl);
    cudaGetSymbolAddress((void**)&wpTh, g_wphiTh); cudaGetSymbolAddress((void**)&wpTl, g_wphiTl);
    cudaGetSymbolAddress((void**)&wmBh, g_wmBh); cudaGetSymbolAddress((void**)&wmBl, g_wmBl);
    cudaGetSymbolAddress((void**)&spTh, g_sppTh); cudaGetSymbolAddress((void**)&spTl, g_sppTl);
    cudaGetSymbolAddress((void**)&kkh, g_kkh);   cudaGetSymbolAddress((void**)&kkl, g_kkl);
    cudaGetSymbolAddress((void**)&vTh, g_vTh);   cudaGetSymbolAddress((void**)&vTl, g_vTl);
    cudaGetSymbolAddress((void**)&PTh, g_PTh);   cudaGetSymbolAddress((void**)&PTl, g_PTl);

    // ---- fork: tconv_x on s1 (depends only on input x) ----
    cudaEventRecord(ev0, 0);
    cudaStreamWaitEvent(s1, ev0, 0);
    tconv_kernel<<<dim3(NN / 32, CC / 32, BB), dim3(32, 8), 0, s1>>>(x, xTh, xTl);
    cudaEventRecord(ev1, s1);

    // ---- main chain on default stream ----
    cudaMemsetAsync(sppI, 0, sizeof(unsigned) * BB * SP * CC, 0);
    pack_kernel<<<(CC * CC + 255) / 256, 256>>>(wth, wg, wphi, wmask);
    tconv_kernel<<<dim3(NN / 32, CC / 32, BB), dim3(32, 8)>>>(y, yTh, yTl);

    // conv GEMM with fused SPP epilogue (M=512, N=4096, K=512)
    gemm_mma<0,0,1><<<dim3(NN / 128, CC / 128, BB), 256, GSMEM_BYTES>>>(
        wh, wl, 0LL, CC, yTh, yTl, (long long)NN * CC, CC,
        nullptr, nullptr, nullptr, 0LL, NN, nullptr, 0LL, CC, sppI);

    // int-mapped maxes -> bf16 hi/lo (+ pad zero)
    sppcvt_kernel<<<(BB * SP * CC + 255) / 256, 256>>>();

    // ---- fork: v chain on s2 (needs pack + sppcvt) ----
    cudaEventRecord(evSpp, 0);
    cudaStreamWaitEvent(s2, evSpp, 0);
    gemm_mma<0,0,0><<<dim3(CC / 128, 1, BB), 256, GSMEM_BYTES, s2>>>(
        spTh + ICN, spTl + ICN, (long long)SP * CC, CC, wmBh, wmBl, 0LL, ICN,
        v, nullptr, nullptr, (long long)SP * CC, CC, nullptr, 0LL, ICN, nullptr);

    // kk GEMM with fused bf16 hi/lo output  (M=128, N=512, K=256)
    gemm_mma<0,1,0><<<dim3(CC / 128, 1, BB), 256, GSMEM_BYTES>>>(
        spTh, spTl, (long long)SP * CC, CC, wpTh, wpTl, 0LL, ICN,
        nullptr, kkh, kkl, (long long)SP * CC, CC, nullptr, 0LL, ICN, nullptr);

    // join: logits GEMM needs xT
    cudaStreamWaitEvent(0, ev1, 0);
    gemm_mma<0,0,0><<<dim3(NN / 128, 1, BB), 256, GSMEM_BYTES>>>(
        kkh, kkl, (long long)SP * CC, CC, xTh, xTl, (long long)NN * CC, CC,
        logits, nullptr, nullptr, (long long)SP * NN, NN, nullptr, 0LL, CC, nullptr);

    rowstat_kernel<<<dim3(SS, BB), 256>>>();

    // ---- fork: vt on s2 (needs vGEMM [s2 order] + rowstat invsum) ----
    cudaEventRecord(evRow, 0);
    cudaStreamWaitEvent(s2, evRow, 0);
    vt_kernel<<<(BB * CC * SP + 255) / 256, 256, 0, s2>>>();
    cudaEventRecord(ev3, s2);

    texp_kernel<<<dim3(NN / 32, BB), 256>>>();

    // join: output GEMM needs vT + PT
    cudaStreamWaitEvent(0, ev3, 0);
    gemm_mma<1,0,0><<<dim3(NN / 128, CC / 128, BB), 256, GSMEM_BYTES>>>(
        vTh, vTl, (long long)CC * SP, SP, PTh, PTl, (long long)NN * SP, SP,
        out, nullptr, nullptr, (long long)CC * NN, NN, x, (long long)CC * NN, SP, nullptr);
}